// round 1
// baseline (speedup 1.0000x reference)
#include <cuda_runtime.h>
#include <math.h>

// ---------------------------------------------------------------------------
// maskedContextModel: B=8, N=2048, C=512, L=5
// Round 0: correct fp32 SGEMM baseline (128x128x8 tiles, 8x8/thread, float4),
// fused epilogues (bias / gelu / residual / attention-mask), row softmax, LN.
// ---------------------------------------------------------------------------

// Scratch (static device globals; allocation inside kernel_launch is forbidden)
__device__ float g_qkv[(size_t)8 * 2048 * 1536];   // qkv activations
__device__ float g_s  [(size_t)8 * 2048 * 2048];   // attention scores / probs
__device__ float g_y  [(size_t)8 * 2048 * 512];    // layernormed features
__device__ float g_h  [(size_t)8 * 2048 * 1024];   // MLP hidden

// EPI: 0 = none, 1 = +bias, 2 = gelu(+bias), 3 = +bias +residual, 4 = attn mask
template <int EPI, bool TB>
__global__ __launch_bounds__(256)
void gemm_k(const float* __restrict__ A, const float* __restrict__ B,
            const float* __restrict__ bias, const float* resid, float* C,
            int M, int N, int K, int lda, int ldb, int ldc,
            long sA, long sB, long sC, long sR, float alpha)
{
    const int BM = 128, BN = 128, BK = 8, TM = 8, TN = 8;
    __shared__ float As[BK][BM];
    __shared__ float Bs[BK][BN];

    const int bz = blockIdx.z;
    A += (long)bz * sA;
    B += (long)bz * sB;
    C += (long)bz * sC;

    const int tid  = threadIdx.x;
    const int brow = blockIdx.y, bcol = blockIdx.x;

    // A-tile loader: 128 rows x 8 k, one float4 per thread (2 threads/row)
    const int aRow = tid >> 1;
    const int aCol = (tid & 1) << 2;
    // B-tile loader (NN): 8 k-rows x 128 cols, one float4 per thread
    const int bRow = tid >> 5;
    const int bCol = (tid & 31) << 2;

    const float* Ab = A + (long)brow * BM * lda;
    const float* Bb = TB ? (B + (long)bcol * BN * ldb) : (B + bcol * BN);

    float acc[TM][TN] = {{0.f}};

    const int ty = tid >> 4, tx = tid & 15;
    const int tr = ty * TM, tc = tx * TN;

    for (int k0 = 0; k0 < K; k0 += BK) {
        float4 a4 = *reinterpret_cast<const float4*>(Ab + (long)aRow * lda + k0 + aCol);
        As[aCol + 0][aRow] = a4.x;
        As[aCol + 1][aRow] = a4.y;
        As[aCol + 2][aRow] = a4.z;
        As[aCol + 3][aRow] = a4.w;
        if (TB) {
            // B is [N x K] row-major (k-contiguous): load like A, store transposed
            float4 b4 = *reinterpret_cast<const float4*>(Bb + (long)aRow * ldb + k0 + aCol);
            Bs[aCol + 0][aRow] = b4.x;
            Bs[aCol + 1][aRow] = b4.y;
            Bs[aCol + 2][aRow] = b4.z;
            Bs[aCol + 3][aRow] = b4.w;
        } else {
            *reinterpret_cast<float4*>(&Bs[bRow][bCol]) =
                *reinterpret_cast<const float4*>(Bb + (long)(k0 + bRow) * ldb + bCol);
        }
        __syncthreads();

#pragma unroll
        for (int k = 0; k < BK; k++) {
            float4 m0 = *reinterpret_cast<const float4*>(&As[k][tr]);
            float4 m1 = *reinterpret_cast<const float4*>(&As[k][tr + 4]);
            float4 n0 = *reinterpret_cast<const float4*>(&Bs[k][tc]);
            float4 n1 = *reinterpret_cast<const float4*>(&Bs[k][tc + 4]);
            float rm[8] = {m0.x, m0.y, m0.z, m0.w, m1.x, m1.y, m1.z, m1.w};
            float rn[8] = {n0.x, n0.y, n0.z, n0.w, n1.x, n1.y, n1.z, n1.w};
#pragma unroll
            for (int m = 0; m < TM; m++)
#pragma unroll
                for (int n = 0; n < TN; n++)
                    acc[m][n] = fmaf(rm[m], rn[n], acc[m][n]);
        }
        __syncthreads();
    }

    // epilogue
#pragma unroll
    for (int m = 0; m < TM; m++) {
        const int gr = brow * BM + tr + m;
#pragma unroll
        for (int n = 0; n < TN; n += 4) {
            float4 o;
            float* po = reinterpret_cast<float*>(&o);
#pragma unroll
            for (int u = 0; u < 4; u++) {
                const int gc = bcol * BN + tc + n + u;
                float v = acc[m][n + u];
                if (EPI == 4) {
                    const int half = N >> 1;
                    const bool allowed = (gr < half) ? (gc < half) : (gc <= gr);
                    v = alpha * v + (allowed ? 0.f : -1000.f);
                } else if (EPI != 0) {
                    v += bias[gc];
                    if (EPI == 2) v = 0.5f * v * (1.f + erff(v * 0.70710678118654752f));
                    if (EPI == 3) v += resid[(long)bz * sR + (long)gr * ldc + gc];
                }
                po[u] = v;
            }
            *reinterpret_cast<float4*>(&C[(long)gr * ldc + bcol * BN + tc + n]) = o;
        }
    }
}

// Row softmax over N=2048, one block (256 thr, 8 elems/thr) per row.
__global__ __launch_bounds__(256)
void softmax_k(float* __restrict__ S)
{
    const int N = 2048;
    float* p = S + (size_t)blockIdx.x * N;
    const int t = threadIdx.x;

    float v[8];
    float mx = -1e30f;
#pragma unroll
    for (int u = 0; u < 8; u++) {
        v[u] = p[t + 256 * u];
        mx = fmaxf(mx, v[u]);
    }
    __shared__ float red[8];
#pragma unroll
    for (int o = 16; o > 0; o >>= 1) mx = fmaxf(mx, __shfl_xor_sync(0xffffffffu, mx, o));
    if ((t & 31) == 0) red[t >> 5] = mx;
    __syncthreads();
    mx = red[0];
#pragma unroll
    for (int i = 1; i < 8; i++) mx = fmaxf(mx, red[i]);

    float s = 0.f;
#pragma unroll
    for (int u = 0; u < 8; u++) {
        v[u] = expf(v[u] - mx);
        s += v[u];
    }
#pragma unroll
    for (int o = 16; o > 0; o >>= 1) s += __shfl_xor_sync(0xffffffffu, s, o);
    __syncthreads();
    if ((t & 31) == 0) red[t >> 5] = s;
    __syncthreads();
    s = red[0];
#pragma unroll
    for (int i = 1; i < 8; i++) s += red[i];

    const float inv = 1.f / s;
#pragma unroll
    for (int u = 0; u < 8; u++) p[t + 256 * u] = v[u] * inv;
}

// LayerNorm over C=512, one block (128 thr, float4/thr) per row.
__global__ __launch_bounds__(128)
void ln_k(const float* __restrict__ X, const float* __restrict__ g,
          const float* __restrict__ b, float* __restrict__ Y)
{
    const int C = 512;
    const float* x = X + (size_t)blockIdx.x * C;
    float* y = Y + (size_t)blockIdx.x * C;
    const int t = threadIdx.x;

    float4 v = *reinterpret_cast<const float4*>(x + t * 4);
    float s = v.x + v.y + v.z + v.w;

    __shared__ float red[4];
#pragma unroll
    for (int o = 16; o > 0; o >>= 1) s += __shfl_xor_sync(0xffffffffu, s, o);
    if ((t & 31) == 0) red[t >> 5] = s;
    __syncthreads();
    const float mean = (red[0] + red[1] + red[2] + red[3]) * (1.f / 512.f);

    const float dx = v.x - mean, dy = v.y - mean, dz = v.z - mean, dw = v.w - mean;
    float q = dx * dx + dy * dy + dz * dz + dw * dw;
#pragma unroll
    for (int o = 16; o > 0; o >>= 1) q += __shfl_xor_sync(0xffffffffu, q, o);
    __syncthreads();
    if ((t & 31) == 0) red[t >> 5] = q;
    __syncthreads();
    const float var = (red[0] + red[1] + red[2] + red[3]) * (1.f / 512.f);
    const float rstd = rsqrtf(var + 1e-5f);

    float4 gg = *reinterpret_cast<const float4*>(g + t * 4);
    float4 bb = *reinterpret_cast<const float4*>(b + t * 4);
    float4 o;
    o.x = dx * rstd * gg.x + bb.x;
    o.y = dy * rstd * gg.y + bb.y;
    o.z = dz * rstd * gg.z + bb.z;
    o.w = dw * rstd * gg.w + bb.w;
    *reinterpret_cast<float4*>(y + t * 4) = o;
}

extern "C" void kernel_launch(void* const* d_in, const int* in_sizes, int n_in,
                              void* d_out, int out_size)
{
    const float* x_in  = (const float*)d_in[0];
    const float* qkv_w = (const float*)d_in[1];
    const float* qkv_b = (const float*)d_in[2];
    const float* ln_g  = (const float*)d_in[3];
    const float* ln_b  = (const float*)d_in[4];
    const float* fc1_w = (const float*)d_in[5];
    const float* fc1_b = (const float*)d_in[6];
    const float* fc2_w = (const float*)d_in[7];
    const float* fc2_b = (const float*)d_in[8];
    float* x = (float*)d_out;

    float *qkv, *S, *y, *h;
    cudaGetSymbolAddress((void**)&qkv, g_qkv);
    cudaGetSymbolAddress((void**)&S,   g_s);
    cudaGetSymbolAddress((void**)&y,   g_y);
    cudaGetSymbolAddress((void**)&h,   g_h);

    const int Bn = 8, Nn = 2048, Cn = 512;
    const long xs = (long)Nn * Cn;
    const float scale = 0.044194173824159216f;  // 512^-0.5

    cudaMemcpyAsync(x, x_in, sizeof(float) * Bn * Nn * Cn, cudaMemcpyDeviceToDevice);

    for (int l = 0; l < 5; l++) {
        // qkv = x @ qkv_w[l] + qkv_b[l]                     (2048x1536x512)
        gemm_k<1, false><<<dim3(12, 16, 8), 256>>>(
            x, qkv_w + (long)l * Cn * 3 * Cn, qkv_b + l * 3 * Cn, nullptr, qkv,
            Nn, 3 * Cn, Cn, Cn, 3 * Cn, 3 * Cn, xs, 0, (long)Nn * 3 * Cn, 0, 1.f);

        // S = scale * q @ k^T + mask bias                   (2048x2048x512)
        gemm_k<4, true><<<dim3(16, 16, 8), 256>>>(
            qkv, qkv + Cn, nullptr, nullptr, S,
            Nn, Nn, Cn, 3 * Cn, 3 * Cn, Nn,
            (long)Nn * 3 * Cn, (long)Nn * 3 * Cn, (long)Nn * Nn, 0, scale);

        // P = softmax(S) row-wise
        softmax_k<<<Bn * Nn, 256>>>(S);

        // x = P @ v                                         (2048x512x2048)
        gemm_k<0, false><<<dim3(4, 16, 8), 256>>>(
            S, qkv + 2 * Cn, nullptr, nullptr, x,
            Nn, Cn, Nn, Nn, 3 * Cn, Cn,
            (long)Nn * Nn, (long)Nn * 3 * Cn, xs, 0, 1.f);

        // y = layernorm(x, g, b)
        ln_k<<<Bn * Nn, 128>>>(x, ln_g + l * Cn, ln_b + l * Cn, y);

        // h = gelu(y @ fc1_w[l] + fc1_b[l])                 (2048x1024x512)
        gemm_k<2, false><<<dim3(8, 16, 8), 256>>>(
            y, fc1_w + (long)l * Cn * 2 * Cn, fc1_b + l * 2 * Cn, nullptr, h,
            Nn, 2 * Cn, Cn, Cn, 2 * Cn, 2 * Cn, xs, 0, (long)Nn * 2 * Cn, 0, 1.f);

        // x = x + h @ fc2_w[l] + fc2_b[l]                   (2048x512x1024)
        gemm_k<3, false><<<dim3(4, 16, 8), 256>>>(
            h, fc2_w + (long)l * 2 * Cn * Cn, fc2_b + l * Cn, x, x,
            Nn, Cn, 2 * Cn, 2 * Cn, Cn, Cn, (long)Nn * 2 * Cn, 0, xs, xs, 1.f);
    }
}

// round 2
// speedup vs baseline: 1.2285x; 1.2285x over previous
#include <cuda_runtime.h>
#include <math.h>

// ---------------------------------------------------------------------------
// maskedContextModel: B=8, N=2048, C=512, L=5
// Round 1: double-buffered SGEMM (1 sync/iter, reg prefetch, padded smem),
// mask-aware block skip in S GEMM, K-truncation in P@V GEMM.
// ---------------------------------------------------------------------------

__device__ float g_qkv[(size_t)8 * 2048 * 1536];   // qkv activations
__device__ float g_s  [(size_t)8 * 2048 * 2048];   // attention scores / probs
__device__ float g_y  [(size_t)8 * 2048 * 512];    // layernormed features
__device__ float g_h  [(size_t)8 * 2048 * 1024];   // MLP hidden

// EPI: 0 = none, 1 = +bias, 2 = gelu(+bias), 3 = +bias +residual, 4 = attn mask
// TB:  B is [N x K] row-major (k-contiguous) -> transpose on smem store
// MASKK: per-block-row K truncation for P@V (shape-specific)
template <int EPI, bool TB, bool MASKK>
__global__ __launch_bounds__(256, 2)
void gemm_k(const float* __restrict__ A, const float* __restrict__ B,
            const float* __restrict__ bias, const float* resid, float* C,
            int M, int N, int K, int lda, int ldb, int ldc,
            long sA, long sB, long sC, long sR, float alpha)
{
    const int BM = 128, BN = 128, BK = 8, TM = 8, TN = 8, PAD = 132;
    __shared__ float As[2][BK][PAD];
    __shared__ float Bs[2][BK][PAD];

    const int bz = blockIdx.z;
    const int tid  = threadIdx.x;
    const int brow = blockIdx.y, bcol = blockIdx.x;

    const int ty = tid >> 4, tx = tid & 15;
    const int tr = ty * TM, tc = tx * TN;

    C += (long)bz * sC;

    // ---- fully masked S-tile: write -1000 and exit (no GEMM) ----
    if (EPI == 4) {
        if ((bcol >= 8 || brow >= 8) && bcol > brow) {
#pragma unroll
            for (int m = 0; m < TM; m++) {
                const long gr = brow * BM + tr + m;
                float4 o = make_float4(-1000.f, -1000.f, -1000.f, -1000.f);
#pragma unroll
                for (int n = 0; n < TN; n += 4)
                    *reinterpret_cast<float4*>(&C[gr * ldc + bcol * BN + tc + n]) = o;
            }
            return;
        }
    }

    A += (long)bz * sA;
    B += (long)bz * sB;

    int Keff = K;
    if (MASKK) Keff = (brow < 8) ? 1024 : (brow + 1) * 128;  // P@V only

    // A-tile loader: 128 rows x 8 k, one float4 per thread (2 threads/row)
    const int aRow = tid >> 1;
    const int aCol = (tid & 1) << 2;
    // B-tile loader (NN): 8 k-rows x 128 cols, one float4 per thread
    const int bRow = tid >> 5;
    const int bCol = (tid & 31) << 2;

    const float* Ab = A + (long)brow * BM * lda;
    const float* Bb = TB ? (B + (long)bcol * BN * ldb) : (B + bcol * BN);

    float acc[TM][TN] = {{0.f}};

    // ---- preload tile 0 ----
    {
        float4 a4 = *reinterpret_cast<const float4*>(Ab + (long)aRow * lda + aCol);
        As[0][aCol + 0][aRow] = a4.x;
        As[0][aCol + 1][aRow] = a4.y;
        As[0][aCol + 2][aRow] = a4.z;
        As[0][aCol + 3][aRow] = a4.w;
        if (TB) {
            float4 b4 = *reinterpret_cast<const float4*>(Bb + (long)aRow * ldb + aCol);
            Bs[0][aCol + 0][aRow] = b4.x;
            Bs[0][aCol + 1][aRow] = b4.y;
            Bs[0][aCol + 2][aRow] = b4.z;
            Bs[0][aCol + 3][aRow] = b4.w;
        } else {
            *reinterpret_cast<float4*>(&Bs[0][bRow][bCol]) =
                *reinterpret_cast<const float4*>(Bb + (long)bRow * ldb + bCol);
        }
    }
    __syncthreads();

    const int nt = Keff / BK;
    int buf = 0;
    for (int t = 0; t < nt; ++t) {
        const bool more = (t + 1) < nt;
        float4 na, nb;
        if (more) {
            const int k0 = (t + 1) * BK;
            na = *reinterpret_cast<const float4*>(Ab + (long)aRow * lda + k0 + aCol);
            nb = TB ? *reinterpret_cast<const float4*>(Bb + (long)aRow * ldb + k0 + aCol)
                    : *reinterpret_cast<const float4*>(Bb + (long)(k0 + bRow) * ldb + bCol);
        }

#pragma unroll
        for (int k = 0; k < BK; k++) {
            float4 m0 = *reinterpret_cast<const float4*>(&As[buf][k][tr]);
            float4 m1 = *reinterpret_cast<const float4*>(&As[buf][k][tr + 4]);
            float4 n0 = *reinterpret_cast<const float4*>(&Bs[buf][k][tc]);
            float4 n1 = *reinterpret_cast<const float4*>(&Bs[buf][k][tc + 4]);
            float rm[8] = {m0.x, m0.y, m0.z, m0.w, m1.x, m1.y, m1.z, m1.w};
            float rn[8] = {n0.x, n0.y, n0.z, n0.w, n1.x, n1.y, n1.z, n1.w};
#pragma unroll
            for (int m = 0; m < TM; m++)
#pragma unroll
                for (int n = 0; n < TN; n++)
                    acc[m][n] = fmaf(rm[m], rn[n], acc[m][n]);
        }

        if (more) {
            const int nb2 = buf ^ 1;
            As[nb2][aCol + 0][aRow] = na.x;
            As[nb2][aCol + 1][aRow] = na.y;
            As[nb2][aCol + 2][aRow] = na.z;
            As[nb2][aCol + 3][aRow] = na.w;
            if (TB) {
                Bs[nb2][aCol + 0][aRow] = nb.x;
                Bs[nb2][aCol + 1][aRow] = nb.y;
                Bs[nb2][aCol + 2][aRow] = nb.z;
                Bs[nb2][aCol + 3][aRow] = nb.w;
            } else {
                *reinterpret_cast<float4*>(&Bs[nb2][bRow][bCol]) =
                    make_float4(nb.x, nb.y, nb.z, nb.w);
            }
            __syncthreads();
            buf = nb2;
        }
    }

    // ---- epilogue ----
#pragma unroll
    for (int m = 0; m < TM; m++) {
        const int gr = brow * BM + tr + m;
#pragma unroll
        for (int n = 0; n < TN; n += 4) {
            float4 o;
            float* po = reinterpret_cast<float*>(&o);
#pragma unroll
            for (int u = 0; u < 4; u++) {
                const int gc = bcol * BN + tc + n + u;
                float v = acc[m][n + u];
                if (EPI == 4) {
                    const int half = N >> 1;
                    const bool allowed = (gr < half) ? (gc < half) : (gc <= gr);
                    v = alpha * v + (allowed ? 0.f : -1000.f);
                } else if (EPI != 0) {
                    v += bias[gc];
                    if (EPI == 2) v = 0.5f * v * (1.f + erff(v * 0.70710678118654752f));
                    if (EPI == 3) v += resid[(long)bz * sR + (long)gr * ldc + gc];
                }
                po[u] = v;
            }
            *reinterpret_cast<float4*>(&C[(long)gr * ldc + bcol * BN + tc + n]) = o;
        }
    }
}

// Row softmax over N=2048, one block (256 thr, 8 elems/thr) per row.
__global__ __launch_bounds__(256)
void softmax_k(float* __restrict__ S)
{
    const int N = 2048;
    float* p = S + (size_t)blockIdx.x * N;
    const int t = threadIdx.x;

    float v[8];
    float mx = -1e30f;
#pragma unroll
    for (int u = 0; u < 8; u++) {
        v[u] = p[t + 256 * u];
        mx = fmaxf(mx, v[u]);
    }
    __shared__ float red[8];
#pragma unroll
    for (int o = 16; o > 0; o >>= 1) mx = fmaxf(mx, __shfl_xor_sync(0xffffffffu, mx, o));
    if ((t & 31) == 0) red[t >> 5] = mx;
    __syncthreads();
    mx = red[0];
#pragma unroll
    for (int i = 1; i < 8; i++) mx = fmaxf(mx, red[i]);

    float s = 0.f;
#pragma unroll
    for (int u = 0; u < 8; u++) {
        v[u] = expf(v[u] - mx);
        s += v[u];
    }
#pragma unroll
    for (int o = 16; o > 0; o >>= 1) s += __shfl_xor_sync(0xffffffffu, s, o);
    __syncthreads();
    if ((t & 31) == 0) red[t >> 5] = s;
    __syncthreads();
    s = red[0];
#pragma unroll
    for (int i = 1; i < 8; i++) s += red[i];

    const float inv = 1.f / s;
#pragma unroll
    for (int u = 0; u < 8; u++) p[t + 256 * u] = v[u] * inv;
}

// LayerNorm over C=512, one block (128 thr, float4/thr) per row.
__global__ __launch_bounds__(128)
void ln_k(const float* __restrict__ X, const float* __restrict__ g,
          const float* __restrict__ b, float* __restrict__ Y)
{
    const int C = 512;
    const float* x = X + (size_t)blockIdx.x * C;
    float* y = Y + (size_t)blockIdx.x * C;
    const int t = threadIdx.x;

    float4 v = *reinterpret_cast<const float4*>(x + t * 4);
    float s = v.x + v.y + v.z + v.w;

    __shared__ float red[4];
#pragma unroll
    for (int o = 16; o > 0; o >>= 1) s += __shfl_xor_sync(0xffffffffu, s, o);
    if ((t & 31) == 0) red[t >> 5] = s;
    __syncthreads();
    const float mean = (red[0] + red[1] + red[2] + red[3]) * (1.f / 512.f);

    const float dx = v.x - mean, dy = v.y - mean, dz = v.z - mean, dw = v.w - mean;
    float q = dx * dx + dy * dy + dz * dz + dw * dw;
#pragma unroll
    for (int o = 16; o > 0; o >>= 1) q += __shfl_xor_sync(0xffffffffu, q, o);
    __syncthreads();
    if ((t & 31) == 0) red[t >> 5] = q;
    __syncthreads();
    const float var = (red[0] + red[1] + red[2] + red[3]) * (1.f / 512.f);
    const float rstd = rsqrtf(var + 1e-5f);

    float4 gg = *reinterpret_cast<const float4*>(g + t * 4);
    float4 bb = *reinterpret_cast<const float4*>(b + t * 4);
    float4 o;
    o.x = dx * rstd * gg.x + bb.x;
    o.y = dy * rstd * gg.y + bb.y;
    o.z = dz * rstd * gg.z + bb.z;
    o.w = dw * rstd * gg.w + bb.w;
    *reinterpret_cast<float4*>(y + t * 4) = o;
}

extern "C" void kernel_launch(void* const* d_in, const int* in_sizes, int n_in,
                              void* d_out, int out_size)
{
    const float* x_in  = (const float*)d_in[0];
    const float* qkv_w = (const float*)d_in[1];
    const float* qkv_b = (const float*)d_in[2];
    const float* ln_g  = (const float*)d_in[3];
    const float* ln_b  = (const float*)d_in[4];
    const float* fc1_w = (const float*)d_in[5];
    const float* fc1_b = (const float*)d_in[6];
    const float* fc2_w = (const float*)d_in[7];
    const float* fc2_b = (const float*)d_in[8];
    float* x = (float*)d_out;

    float *qkv, *S, *y, *h;
    cudaGetSymbolAddress((void**)&qkv, g_qkv);
    cudaGetSymbolAddress((void**)&S,   g_s);
    cudaGetSymbolAddress((void**)&y,   g_y);
    cudaGetSymbolAddress((void**)&h,   g_h);

    const int Bn = 8, Nn = 2048, Cn = 512;
    const long xs = (long)Nn * Cn;
    const float scale = 0.044194173824159216f;  // 512^-0.5

    cudaMemcpyAsync(x, x_in, sizeof(float) * Bn * Nn * Cn, cudaMemcpyDeviceToDevice);

    for (int l = 0; l < 5; l++) {
        // qkv = x @ qkv_w[l] + qkv_b[l]                     (2048x1536x512)
        gemm_k<1, false, false><<<dim3(12, 16, 8), 256>>>(
            x, qkv_w + (long)l * Cn * 3 * Cn, qkv_b + l * 3 * Cn, nullptr, qkv,
            Nn, 3 * Cn, Cn, Cn, 3 * Cn, 3 * Cn, xs, 0, (long)Nn * 3 * Cn, 0, 1.f);

        // S = scale * q @ k^T + mask bias                   (2048x2048x512)
        gemm_k<4, true, false><<<dim3(16, 16, 8), 256>>>(
            qkv, qkv + Cn, nullptr, nullptr, S,
            Nn, Nn, Cn, 3 * Cn, 3 * Cn, Nn,
            (long)Nn * 3 * Cn, (long)Nn * 3 * Cn, (long)Nn * Nn, 0, scale);

        // P = softmax(S) row-wise
        softmax_k<<<Bn * Nn, 256>>>(S);

        // x = P @ v   (K truncated per block row)           (2048x512x<=2048)
        gemm_k<0, false, true><<<dim3(4, 16, 8), 256>>>(
            S, qkv + 2 * Cn, nullptr, nullptr, x,
            Nn, Cn, Nn, Nn, 3 * Cn, Cn,
            (long)Nn * Nn, (long)Nn * 3 * Cn, xs, 0, 1.f);

        // y = layernorm(x, g, b)
        ln_k<<<Bn * Nn, 128>>>(x, ln_g + l * Cn, ln_b + l * Cn, y);

        // h = gelu(y @ fc1_w[l] + fc1_b[l])                 (2048x1024x512)
        gemm_k<2, false, false><<<dim3(8, 16, 8), 256>>>(
            y, fc1_w + (long)l * Cn * 2 * Cn, fc1_b + l * 2 * Cn, nullptr, h,
            Nn, 2 * Cn, Cn, Cn, 2 * Cn, 2 * Cn, xs, 0, (long)Nn * 2 * Cn, 0, 1.f);

        // x = x + h @ fc2_w[l] + fc2_b[l]                   (2048x512x1024)
        gemm_k<3, false, false><<<dim3(4, 16, 8), 256>>>(
            h, fc2_w + (long)l * 2 * Cn * Cn, fc2_b + l * Cn, x, x,
            Nn, Cn, 2 * Cn, 2 * Cn, Cn, Cn, (long)Nn * 2 * Cn, 0, xs, xs, 1.f);
    }
}

// round 8
// speedup vs baseline: 1.4919x; 1.2144x over previous
#include <cuda_runtime.h>
#include <math.h>

// ---------------------------------------------------------------------------
// maskedContextModel: B=8, N=2048, C=512, L=5
// Round 3: 3xTF32 tensor-core GEMM (hi/lo split, fp32-grade accuracy),
// 128x128x16 CTA tile, 8 warps (64x32 warp tile), double-buffered smem.
// Mask block-skip + K-truncation retained.
// ---------------------------------------------------------------------------

__device__ float g_qkv[(size_t)8 * 2048 * 1536];   // qkv activations
__device__ float g_s  [(size_t)8 * 2048 * 2048];   // attention scores / probs
__device__ float g_y  [(size_t)8 * 2048 * 512];    // layernormed features
__device__ float g_h  [(size_t)8 * 2048 * 1024];   // MLP hidden

__device__ __forceinline__ unsigned to_tf32(float f) {
    unsigned r;
    asm("cvt.rna.tf32.f32 %0, %1;" : "=r"(r) : "f"(f));
    return r;
}
__device__ __forceinline__ void split_tf32(float f, unsigned& hi, unsigned& lo) {
    hi = to_tf32(f);
    lo = to_tf32(f - __uint_as_float(hi));
}

__device__ __forceinline__ void mma_tf32(float& c0, float& c1, float& c2, float& c3,
                                         unsigned a0, unsigned a1, unsigned a2, unsigned a3,
                                         unsigned b0, unsigned b1) {
    asm volatile(
        "mma.sync.aligned.m16n8k8.row.col.f32.tf32.tf32.f32 "
        "{%0,%1,%2,%3}, {%4,%5,%6,%7}, {%8,%9}, {%0,%1,%2,%3};"
        : "+f"(c0), "+f"(c1), "+f"(c2), "+f"(c3)
        : "r"(a0), "r"(a1), "r"(a2), "r"(a3), "r"(b0), "r"(b1));
}

#define BKPAD (16 * 136)
static const int GEMM_SMEM_BYTES = 8 * BKPAD * 4;   // 69,632 B

// EPI: 0=none, 1=+bias, 2=gelu(+bias), 3=+bias+residual, 4=attn mask
// TB: B is [N x K] row-major (k-contiguous)
// MASKK: per-block-row K truncation for P@V
template <int EPI, bool TB, bool MASKK>
__global__ __launch_bounds__(256)
void gemm_k(const float* __restrict__ A, const float* __restrict__ B,
            const float* __restrict__ bias, const float* resid, float* C,
            int M, int N, int K, int lda, int ldb, int ldc,
            long sA, long sB, long sC, long sR, float alpha)
{
    const int BM = 128, BN = 128, BK = 16, PAD = 136;
    extern __shared__ unsigned dynsmem[];
    unsigned* AsH = dynsmem;                // [2][BK*PAD] k-major [k][m]
    unsigned* AsL = AsH + 2 * BKPAD;
    unsigned* BsH = AsL + 2 * BKPAD;        // [2][BK*PAD] k-major [k][n]
    unsigned* BsL = BsH + 2 * BKPAD;

    const int bz   = blockIdx.z;
    const int tid  = threadIdx.x;
    const int brow = blockIdx.y, bcol = blockIdx.x;

    const int lane  = tid & 31;
    const int warp  = tid >> 5;
    const int warpM = warp & 1;          // 2 warp-rows x 64
    const int warpN = warp >> 1;         // 4 warp-cols x 32
    const int kA    = lane & 3;          // fragment k index
    const int grp   = lane >> 2;         // fragment row/col group
    const int mBase = warpM * 64;
    const int nBase = warpN * 32;

    C += (long)bz * sC;

    // ---- fully masked S-tile: fill -1000, skip GEMM ----
    if (EPI == 4) {
        if ((bcol >= 8 || brow >= 8) && bcol > brow) {
            float2 mk = make_float2(-1000.f, -1000.f);
#pragma unroll
            for (int mt = 0; mt < 4; mt++) {
                const long gr0 = brow * BM + mBase + mt * 16 + grp;
#pragma unroll
                for (int nt = 0; nt < 4; nt++) {
                    const int gc = bcol * BN + nBase + nt * 8 + kA * 2;
                    *reinterpret_cast<float2*>(&C[gr0 * ldc + gc]) = mk;
                    *reinterpret_cast<float2*>(&C[(gr0 + 8) * ldc + gc]) = mk;
                }
            }
            return;
        }
    }

    A += (long)bz * sA;
    B += (long)bz * sB;

    int Keff = K;
    if (MASKK) Keff = (brow < 8) ? 1024 : (brow + 1) * 128;

    // ---- gmem loader coordinates ----
    const int aRow  = tid >> 1;          // 0..127
    const int aHalf = tid & 1;           // 8-wide k half
    const float* Ab = A + (long)brow * BM * lda + (long)aRow * lda + aHalf * 8;
    const int bKr = tid >> 4;            // 0..15
    const int bNc = (tid & 15) * 4;      // 0..60 (and +64)
    const float* BbNN = B + bcol * BN + (long)bKr * ldb + bNc;
    const float* BbTB = B + (long)bcol * BN * ldb + (long)aRow * ldb + aHalf * 8;

    float c[4][4][4];
#pragma unroll
    for (int mt = 0; mt < 4; mt++)
#pragma unroll
        for (int nt = 0; nt < 4; nt++)
#pragma unroll
            for (int i = 0; i < 4; i++) c[mt][nt][i] = 0.f;

    const int aOff = (aHalf * 8) * PAD + aRow;   // column-major-in-tile store base

    // ---- stage 0 ----
    {
        float4 fa0 = *reinterpret_cast<const float4*>(Ab);
        float4 fa1 = *reinterpret_cast<const float4*>(Ab + 4);
        const float av[8] = {fa0.x, fa0.y, fa0.z, fa0.w, fa1.x, fa1.y, fa1.z, fa1.w};
#pragma unroll
        for (int i = 0; i < 8; i++) {
            unsigned h, l;
            split_tf32(av[i], h, l);
            AsH[aOff + i * PAD] = h;
            AsL[aOff + i * PAD] = l;
        }
        if (TB) {
            float4 fb0 = *reinterpret_cast<const float4*>(BbTB);
            float4 fb1 = *reinterpret_cast<const float4*>(BbTB + 4);
            const float bv[8] = {fb0.x, fb0.y, fb0.z, fb0.w, fb1.x, fb1.y, fb1.z, fb1.w};
#pragma unroll
            for (int i = 0; i < 8; i++) {
                unsigned h, l;
                split_tf32(bv[i], h, l);
                BsH[aOff + i * PAD] = h;
                BsL[aOff + i * PAD] = l;
            }
        } else {
            float4 fb0 = *reinterpret_cast<const float4*>(BbNN);
            float4 fb1 = *reinterpret_cast<const float4*>(BbNN + 64);
            uint4 h0, l0, h1, l1;
            split_tf32(fb0.x, h0.x, l0.x); split_tf32(fb0.y, h0.y, l0.y);
            split_tf32(fb0.z, h0.z, l0.z); split_tf32(fb0.w, h0.w, l0.w);
            split_tf32(fb1.x, h1.x, l1.x); split_tf32(fb1.y, h1.y, l1.y);
            split_tf32(fb1.z, h1.z, l1.z); split_tf32(fb1.w, h1.w, l1.w);
            *reinterpret_cast<uint4*>(&BsH[bKr * PAD + bNc]) = h0;
            *reinterpret_cast<uint4*>(&BsL[bKr * PAD + bNc]) = l0;
            *reinterpret_cast<uint4*>(&BsH[bKr * PAD + bNc + 64]) = h1;
            *reinterpret_cast<uint4*>(&BsL[bKr * PAD + bNc + 64]) = l1;
        }
    }
    __syncthreads();

    const int nt_stages = Keff / BK;
    int buf = 0;
    for (int t = 0; t < nt_stages; ++t) {
        const bool more = (t + 1) < nt_stages;
        float4 fa0, fa1, fb0, fb1;
        if (more) {
            const int k0 = (t + 1) * BK;
            fa0 = *reinterpret_cast<const float4*>(Ab + k0);
            fa1 = *reinterpret_cast<const float4*>(Ab + k0 + 4);
            if (TB) {
                fb0 = *reinterpret_cast<const float4*>(BbTB + k0);
                fb1 = *reinterpret_cast<const float4*>(BbTB + k0 + 4);
            } else {
                fb0 = *reinterpret_cast<const float4*>(BbNN + (long)k0 * ldb);
                fb1 = *reinterpret_cast<const float4*>(BbNN + (long)k0 * ldb + 64);
            }
        }

        // ---- compute: 2 k-steps of 8, 3 MMAs each (hi*hi, hi*lo, lo*hi) ----
        const unsigned* AH = AsH + buf * BKPAD;
        const unsigned* AL = AsL + buf * BKPAD;
        const unsigned* BH = BsH + buf * BKPAD;
        const unsigned* BL = BsL + buf * BKPAD;
#pragma unroll
        for (int ks = 0; ks < 2; ks++) {
            const int kb = (ks * 8 + kA) * PAD;
            unsigned ah[4][4], bh[4][2];
#pragma unroll
            for (int mt = 0; mt < 4; mt++) {
                const int m0 = mBase + mt * 16 + grp;
                ah[mt][0] = AH[kb + m0];
                ah[mt][1] = AH[kb + m0 + 8];
                ah[mt][2] = AH[kb + 4 * PAD + m0];
                ah[mt][3] = AH[kb + 4 * PAD + m0 + 8];
            }
#pragma unroll
            for (int nt = 0; nt < 4; nt++) {
                const int n0 = nBase + nt * 8 + grp;
                bh[nt][0] = BH[kb + n0];
                bh[nt][1] = BH[kb + 4 * PAD + n0];
            }
#pragma unroll
            for (int mt = 0; mt < 4; mt++)
#pragma unroll
                for (int nt = 0; nt < 4; nt++)
                    mma_tf32(c[mt][nt][0], c[mt][nt][1], c[mt][nt][2], c[mt][nt][3],
                             ah[mt][0], ah[mt][1], ah[mt][2], ah[mt][3],
                             bh[nt][0], bh[nt][1]);

            unsigned bl[4][2];
#pragma unroll
            for (int nt = 0; nt < 4; nt++) {
                const int n0 = nBase + nt * 8 + grp;
                bl[nt][0] = BL[kb + n0];
                bl[nt][1] = BL[kb + 4 * PAD + n0];
            }
#pragma unroll
            for (int mt = 0; mt < 4; mt++)
#pragma unroll
                for (int nt = 0; nt < 4; nt++)
                    mma_tf32(c[mt][nt][0], c[mt][nt][1], c[mt][nt][2], c[mt][nt][3],
                             ah[mt][0], ah[mt][1], ah[mt][2], ah[mt][3],
                             bl[nt][0], bl[nt][1]);

            unsigned al[4][4];
#pragma unroll
            for (int mt = 0; mt < 4; mt++) {
                const int m0 = mBase + mt * 16 + grp;
                al[mt][0] = AL[kb + m0];
                al[mt][1] = AL[kb + m0 + 8];
                al[mt][2] = AL[kb + 4 * PAD + m0];
                al[mt][3] = AL[kb + 4 * PAD + m0 + 8];
            }
#pragma unroll
            for (int mt = 0; mt < 4; mt++)
#pragma unroll
                for (int nt = 0; nt < 4; nt++)
                    mma_tf32(c[mt][nt][0], c[mt][nt][1], c[mt][nt][2], c[mt][nt][3],
                             al[mt][0], al[mt][1], al[mt][2], al[mt][3],
                             bh[nt][0], bh[nt][1]);
        }

        if (more) {
            const int nb = buf ^ 1;
            unsigned* AHn = AsH + nb * BKPAD;
            unsigned* ALn = AsL + nb * BKPAD;
            unsigned* BHn = BsH + nb * BKPAD;
            unsigned* BLn = BsL + nb * BKPAD;
            const float av[8] = {fa0.x, fa0.y, fa0.z, fa0.w, fa1.x, fa1.y, fa1.z, fa1.w};
#pragma unroll
            for (int i = 0; i < 8; i++) {
                unsigned h, l;
                split_tf32(av[i], h, l);
                AHn[aOff + i * PAD] = h;
                ALn[aOff + i * PAD] = l;
            }
            if (TB) {
                const float bv[8] = {fb0.x, fb0.y, fb0.z, fb0.w, fb1.x, fb1.y, fb1.z, fb1.w};
#pragma unroll
                for (int i = 0; i < 8; i++) {
                    unsigned h, l;
                    split_tf32(bv[i], h, l);
                    BHn[aOff + i * PAD] = h;
                    BLn[aOff + i * PAD] = l;
                }
            } else {
                uint4 h0, l0, h1, l1;
                split_tf32(fb0.x, h0.x, l0.x); split_tf32(fb0.y, h0.y, l0.y);
                split_tf32(fb0.z, h0.z, l0.z); split_tf32(fb0.w, h0.w, l0.w);
                split_tf32(fb1.x, h1.x, l1.x); split_tf32(fb1.y, h1.y, l1.y);
                split_tf32(fb1.z, h1.z, l1.z); split_tf32(fb1.w, h1.w, l1.w);
                *reinterpret_cast<uint4*>(&BHn[bKr * PAD + bNc]) = h0;
                *reinterpret_cast<uint4*>(&BLn[bKr * PAD + bNc]) = l0;
                *reinterpret_cast<uint4*>(&BHn[bKr * PAD + bNc + 64]) = h1;
                *reinterpret_cast<uint4*>(&BLn[bKr * PAD + bNc + 64]) = l1;
            }
            __syncthreads();
            buf = nb;
        }
    }

    // ---- epilogue ----
#pragma unroll
    for (int mt = 0; mt < 4; mt++) {
        const int gr0 = brow * BM + mBase + mt * 16 + grp;
#pragma unroll
        for (int nt = 0; nt < 4; nt++) {
            const int gc = bcol * BN + nBase + nt * 8 + kA * 2;
#pragma unroll
            for (int h = 0; h < 2; h++) {
                const int gr = gr0 + h * 8;
                float v0 = c[mt][nt][h * 2 + 0];
                float v1 = c[mt][nt][h * 2 + 1];
                if (EPI == 4) {
                    const int half = N >> 1;
                    const bool ok0 = (gr < half) ? (gc < half) : (gc <= gr);
                    const bool ok1 = (gr < half) ? (gc + 1 < half) : (gc + 1 <= gr);
                    v0 = alpha * v0 + (ok0 ? 0.f : -1000.f);
                    v1 = alpha * v1 + (ok1 ? 0.f : -1000.f);
                } else if (EPI != 0) {
                    v0 += bias[gc];
                    v1 += bias[gc + 1];
                    if (EPI == 2) {
                        v0 = 0.5f * v0 * (1.f + erff(v0 * 0.70710678118654752f));
                        v1 = 0.5f * v1 * (1.f + erff(v1 * 0.70710678118654752f));
                    }
                    if (EPI == 3) {
                        const float* rr = resid + (long)bz * sR + (long)gr * ldc + gc;
                        v0 += rr[0];
                        v1 += rr[1];
                    }
                }
                *reinterpret_cast<float2*>(&C[(long)gr * ldc + gc]) = make_float2(v0, v1);
            }
        }
    }
}

// Row softmax over N=2048, one block (256 thr, 8 elems/thr) per row.
__global__ __launch_bounds__(256)
void softmax_k(float* __restrict__ S)
{
    const int N = 2048;
    float* p = S + (size_t)blockIdx.x * N;
    const int t = threadIdx.x;

    float v[8];
    float mx = -1e30f;
#pragma unroll
    for (int u = 0; u < 8; u++) {
        v[u] = p[t + 256 * u];
        mx = fmaxf(mx, v[u]);
    }
    __shared__ float red[8];
#pragma unroll
    for (int o = 16; o > 0; o >>= 1) mx = fmaxf(mx, __shfl_xor_sync(0xffffffffu, mx, o));
    if ((t & 31) == 0) red[t >> 5] = mx;
    __syncthreads();
    mx = red[0];
#pragma unroll
    for (int i = 1; i < 8; i++) mx = fmaxf(mx, red[i]);

    float s = 0.f;
#pragma unroll
    for (int u = 0; u < 8; u++) {
        v[u] = expf(v[u] - mx);
        s += v[u];
    }
#pragma unroll
    for (int o = 16; o > 0; o >>= 1) s += __shfl_xor_sync(0xffffffffu, s, o);
    __syncthreads();
    if ((t & 31) == 0) red[t >> 5] = s;
    __syncthreads();
    s = red[0];
#pragma unroll
    for (int i = 1; i < 8; i++) s += red[i];

    const float inv = 1.f / s;
#pragma unroll
    for (int u = 0; u < 8; u++) p[t + 256 * u] = v[u] * inv;
}

// LayerNorm over C=512, one block (128 thr, float4/thr) per row.
__global__ __launch_bounds__(128)
void ln_k(const float* __restrict__ X, const float* __restrict__ g,
          const float* __restrict__ b, float* __restrict__ Y)
{
    const int C = 512;
    const float* x = X + (size_t)blockIdx.x * C;
    float* y = Y + (size_t)blockIdx.x * C;
    const int t = threadIdx.x;

    float4 v = *reinterpret_cast<const float4*>(x + t * 4);
    float s = v.x + v.y + v.z + v.w;

    __shared__ float red[4];
#pragma unroll
    for (int o = 16; o > 0; o >>= 1) s += __shfl_xor_sync(0xffffffffu, s, o);
    if ((t & 31) == 0) red[t >> 5] = s;
    __syncthreads();
    const float mean = (red[0] + red[1] + red[2] + red[3]) * (1.f / 512.f);

    const float dx = v.x - mean, dy = v.y - mean, dz = v.z - mean, dw = v.w - mean;
    float q = dx * dx + dy * dy + dz * dz + dw * dw;
#pragma unroll
    for (int o = 16; o > 0; o >>= 1) q += __shfl_xor_sync(0xffffffffu, q, o);
    __syncthreads();
    if ((t & 31) == 0) red[t >> 5] = q;
    __syncthreads();
    const float var = (red[0] + red[1] + red[2] + red[3]) * (1.f / 512.f);
    const float rstd = rsqrtf(var + 1e-5f);

    float4 gg = *reinterpret_cast<const float4*>(g + t * 4);
    float4 bb = *reinterpret_cast<const float4*>(b + t * 4);
    float4 o;
    o.x = dx * rstd * gg.x + bb.x;
    o.y = dy * rstd * gg.y + bb.y;
    o.z = dz * rstd * gg.z + bb.z;
    o.w = dw * rstd * gg.w + bb.w;
    *reinterpret_cast<float4*>(y + t * 4) = o;
}

extern "C" void kernel_launch(void* const* d_in, const int* in_sizes, int n_in,
                              void* d_out, int out_size)
{
    const float* x_in  = (const float*)d_in[0];
    const float* qkv_w = (const float*)d_in[1];
    const float* qkv_b = (const float*)d_in[2];
    const float* ln_g  = (const float*)d_in[3];
    const float* ln_b  = (const float*)d_in[4];
    const float* fc1_w = (const float*)d_in[5];
    const float* fc1_b = (const float*)d_in[6];
    const float* fc2_w = (const float*)d_in[7];
    const float* fc2_b = (const float*)d_in[8];
    float* x = (float*)d_out;

    float *qkv, *S, *y, *h;
    cudaGetSymbolAddress((void**)&qkv, g_qkv);
    cudaGetSymbolAddress((void**)&S,   g_s);
    cudaGetSymbolAddress((void**)&y,   g_y);
    cudaGetSymbolAddress((void**)&h,   g_h);

    const int Bn = 8, Nn = 2048, Cn = 512;
    const long xs = (long)Nn * Cn;
    const float scale = 0.044194173824159216f;  // 512^-0.5

    cudaFuncSetAttribute(gemm_k<1, false, false>,
                         cudaFuncAttributeMaxDynamicSharedMemorySize, GEMM_SMEM_BYTES);
    cudaFuncSetAttribute(gemm_k<4, true,  false>,
                         cudaFuncAttributeMaxDynamicSharedMemorySize, GEMM_SMEM_BYTES);
    cudaFuncSetAttribute(gemm_k<0, false, true>,
                         cudaFuncAttributeMaxDynamicSharedMemorySize, GEMM_SMEM_BYTES);
    cudaFuncSetAttribute(gemm_k<2, false, false>,
                         cudaFuncAttributeMaxDynamicSharedMemorySize, GEMM_SMEM_BYTES);
    cudaFuncSetAttribute(gemm_k<3, false, false>,
                         cudaFuncAttributeMaxDynamicSharedMemorySize, GEMM_SMEM_BYTES);

    cudaMemcpyAsync(x, x_in, sizeof(float) * Bn * Nn * Cn, cudaMemcpyDeviceToDevice);

    for (int l = 0; l < 5; l++) {
        // qkv = x @ qkv_w[l] + qkv_b[l]                     (2048x1536x512)
        gemm_k<1, false, false><<<dim3(12, 16, 8), 256, GEMM_SMEM_BYTES>>>(
            x, qkv_w + (long)l * Cn * 3 * Cn, qkv_b + l * 3 * Cn, nullptr, qkv,
            Nn, 3 * Cn, Cn, Cn, 3 * Cn, 3 * Cn, xs, 0, (long)Nn * 3 * Cn, 0, 1.f);

        // S = scale * q @ k^T + mask bias                   (2048x2048x512)
        gemm_k<4, true, false><<<dim3(16, 16, 8), 256, GEMM_SMEM_BYTES>>>(
            qkv, qkv + Cn, nullptr, nullptr, S,
            Nn, Nn, Cn, 3 * Cn, 3 * Cn, Nn,
            (long)Nn * 3 * Cn, (long)Nn * 3 * Cn, (long)Nn * Nn, 0, scale);

        // P = softmax(S) row-wise
        softmax_k<<<Bn * Nn, 256>>>(S);

        // x = P @ v   (K truncated per block row)           (2048x512x<=2048)
        gemm_k<0, false, true><<<dim3(4, 16, 8), 256, GEMM_SMEM_BYTES>>>(
            S, qkv + 2 * Cn, nullptr, nullptr, x,
            Nn, Cn, Nn, Nn, 3 * Cn, Cn,
            (long)Nn * Nn, (long)Nn * 3 * Cn, xs, 0, 1.f);

        // y = layernorm(x, g, b)
        ln_k<<<Bn * Nn, 128>>>(x, ln_g + l * Cn, ln_b + l * Cn, y);

        // h = gelu(y @ fc1_w[l] + fc1_b[l])                 (2048x1024x512)
        gemm_k<2, false, false><<<dim3(8, 16, 8), 256, GEMM_SMEM_BYTES>>>(
            y, fc1_w + (long)l * Cn * 2 * Cn, fc1_b + l * 2 * Cn, nullptr, h,
            Nn, 2 * Cn, Cn, Cn, 2 * Cn, 2 * Cn, xs, 0, (long)Nn * 2 * Cn, 0, 1.f);

        // x = x + h @ fc2_w[l] + fc2_b[l]                   (2048x512x1024)
        gemm_k<3, false, false><<<dim3(4, 16, 8), 256, GEMM_SMEM_BYTES>>>(
            h, fc2_w + (long)l * 2 * Cn * Cn, fc2_b + l * Cn, x, x,
            Nn, Cn, 2 * Cn, 2 * Cn, Cn, Cn, (long)Nn * 2 * Cn, 0, xs, xs, 1.f);
    }
}

// round 10
// speedup vs baseline: 1.5913x; 1.0666x over previous
#include <cuda_runtime.h>
#include <math.h>

// ---------------------------------------------------------------------------
// maskedContextModel: B=8, N=2048, C=512, L=5
// Round 8: 3xTF32 GEMM, fp32 smem tiles + in-register hi/lo split,
// cp.async double-buffered pipeline, 2 CTAs/SM. Mask skip + K-trunc kept.
// ---------------------------------------------------------------------------

__device__ float g_qkv[(size_t)8 * 2048 * 1536];
__device__ float g_s  [(size_t)8 * 2048 * 2048];
__device__ float g_y  [(size_t)8 * 2048 * 512];
__device__ float g_h  [(size_t)8 * 2048 * 1024];

__device__ __forceinline__ unsigned to_tf32(float f) {
    unsigned r;
    asm("cvt.rna.tf32.f32 %0, %1;" : "=r"(r) : "f"(f));
    return r;
}
__device__ __forceinline__ void split_tf32(float f, unsigned& hi, unsigned& lo) {
    hi = to_tf32(f);
    lo = to_tf32(f - __uint_as_float(hi));
}

__device__ __forceinline__ void mma_tf32(float& c0, float& c1, float& c2, float& c3,
                                         unsigned a0, unsigned a1, unsigned a2, unsigned a3,
                                         unsigned b0, unsigned b1) {
    asm volatile(
        "mma.sync.aligned.m16n8k8.row.col.f32.tf32.tf32.f32 "
        "{%0,%1,%2,%3}, {%4,%5,%6,%7}, {%8,%9}, {%0,%1,%2,%3};"
        : "+f"(c0), "+f"(c1), "+f"(c2), "+f"(c3)
        : "r"(a0), "r"(a1), "r"(a2), "r"(a3), "r"(b0), "r"(b1));
}

__device__ __forceinline__ void cp16(float* s, const float* g) {
    unsigned sa = (unsigned)__cvta_generic_to_shared(s);
    asm volatile("cp.async.cg.shared.global [%0], [%1], 16;" :: "r"(sa), "l"(g));
}
__device__ __forceinline__ void cp_commit() { asm volatile("cp.async.commit_group;"); }
__device__ __forceinline__ void cp_wait0()  { asm volatile("cp.async.wait_group 0;" ::: "memory"); }

// A / TB-B tile: [128 rows][16 k] fp32, row pitch 20 (bank-conflict-free frags)
// NN-B tile:     [16 k][128 n] fp32, row pitch 136
#define APITCH 20
#define BPITCH 136
#define TILEF  2560   // floats per buffer (max of 128*20, 16*136)

// EPI: 0=none, 1=+bias, 2=gelu(+bias), 3=+bias+residual, 4=attn mask
// TB: B is [N x K] row-major (k-contiguous); MASKK: P@V K truncation
template <int EPI, bool TB, bool MASKK>
__global__ __launch_bounds__(256, 2)
void gemm_k(const float* __restrict__ A, const float* __restrict__ B,
            const float* __restrict__ bias, const float* resid, float* C,
            int M, int N, int K, int lda, int ldb, int ldc,
            long sA, long sB, long sC, long sR, float alpha)
{
    const int BM = 128, BN = 128, BK = 16;
    __shared__ float As[2][TILEF];
    __shared__ float Bs[2][TILEF];

    const int bz   = blockIdx.z;
    const int tid  = threadIdx.x;
    const int brow = blockIdx.y, bcol = blockIdx.x;

    const int lane  = tid & 31;
    const int warp  = tid >> 5;
    const int warpM = warp & 1;
    const int warpN = warp >> 1;
    const int kA    = lane & 3;
    const int grp   = lane >> 2;
    const int mBase = warpM * 64;
    const int nBase = warpN * 32;

    C += (long)bz * sC;

    if (EPI == 4) {
        if ((bcol >= 8 || brow >= 8) && bcol > brow) {
            float2 mk = make_float2(-1000.f, -1000.f);
#pragma unroll
            for (int mt = 0; mt < 4; mt++) {
                const long gr0 = brow * BM + mBase + mt * 16 + grp;
#pragma unroll
                for (int nt = 0; nt < 4; nt++) {
                    const int gc = bcol * BN + nBase + nt * 8 + kA * 2;
                    *reinterpret_cast<float2*>(&C[gr0 * ldc + gc]) = mk;
                    *reinterpret_cast<float2*>(&C[(gr0 + 8) * ldc + gc]) = mk;
                }
            }
            return;
        }
    }

    A += (long)bz * sA;
    B += (long)bz * sB;

    int Keff = K;
    if (MASKK) Keff = (brow < 8) ? 1024 : (brow + 1) * 128;

    // ---- loader coordinates ----
    const int aRow   = tid >> 1;             // 0..127
    const int aChunk = (tid & 1) * 8;        // float offset 0 / 8
    const float* Ab  = A + (long)(brow * BM + aRow) * lda + aChunk;
    float* AsDst0 = &As[0][aRow * APITCH + aChunk];
    float* AsDst1 = &As[1][aRow * APITCH + aChunk];

    const int bKr  = tid >> 4;               // 0..15
    const int bNc8 = (tid & 15) * 8;         // 0..120
    const float* BbNN = B + bcol * BN + (long)bKr * ldb + bNc8;
    const float* BbTB = B + (long)(bcol * BN + aRow) * ldb + aChunk;
    float* BsDstNN0 = &Bs[0][bKr * BPITCH + bNc8];
    float* BsDstNN1 = &Bs[1][bKr * BPITCH + bNc8];
    float* BsDstTB0 = &Bs[0][aRow * APITCH + aChunk];
    float* BsDstTB1 = &Bs[1][aRow * APITCH + aChunk];

    float c[4][4][4];
#pragma unroll
    for (int mt = 0; mt < 4; mt++)
#pragma unroll
        for (int nt = 0; nt < 4; nt++)
#pragma unroll
            for (int i = 0; i < 4; i++) c[mt][nt][i] = 0.f;

    // ---- preload stage 0 ----
    {
        cp16(AsDst0, Ab);
        cp16(AsDst0 + 4, Ab + 4);
        if (TB) {
            cp16(BsDstTB0, BbTB);
            cp16(BsDstTB0 + 4, BbTB + 4);
        } else {
            cp16(BsDstNN0, BbNN);
            cp16(BsDstNN0 + 4, BbNN + 4);
        }
        cp_commit();
        cp_wait0();
    }
    __syncthreads();

    const int nstages = Keff / BK;
    int buf = 0;
    for (int t = 0; t < nstages; ++t) {
        const bool more = (t + 1) < nstages;
        if (more) {
            const int k0 = (t + 1) * BK;
            float* ad = buf ? AsDst0 : AsDst1;
            cp16(ad, Ab + k0);
            cp16(ad + 4, Ab + k0 + 4);
            if (TB) {
                float* bd = buf ? BsDstTB0 : BsDstTB1;
                cp16(bd, BbTB + k0);
                cp16(bd + 4, BbTB + k0 + 4);
            } else {
                float* bd = buf ? BsDstNN0 : BsDstNN1;
                cp16(bd, BbNN + (long)k0 * ldb);
                cp16(bd + 4, BbNN + (long)k0 * ldb + 4);
            }
            cp_commit();
        }

        const float* Abuf = As[buf];
        const float* Bbuf = Bs[buf];
#pragma unroll
        for (int ks = 0; ks < 2; ks++) {
            const int kk = ks * 8 + kA;
            unsigned ah[4][4], al[4][4];
#pragma unroll
            for (int mt = 0; mt < 4; mt++) {
                const float* ar = &Abuf[(mBase + mt * 16 + grp) * APITCH + kk];
                split_tf32(ar[0],            ah[mt][0], al[mt][0]);
                split_tf32(ar[8 * APITCH],   ah[mt][1], al[mt][1]);
                split_tf32(ar[4],            ah[mt][2], al[mt][2]);
                split_tf32(ar[8 * APITCH + 4], ah[mt][3], al[mt][3]);
            }
            unsigned bh[4][2], bl[4][2];
#pragma unroll
            for (int nt = 0; nt < 4; nt++) {
                if (TB) {
                    const float* br = &Bbuf[(nBase + nt * 8 + grp) * APITCH + kk];
                    split_tf32(br[0], bh[nt][0], bl[nt][0]);
                    split_tf32(br[4], bh[nt][1], bl[nt][1]);
                } else {
                    const float* br = &Bbuf[kk * BPITCH + nBase + nt * 8 + grp];
                    split_tf32(br[0],          bh[nt][0], bl[nt][0]);
                    split_tf32(br[4 * BPITCH], bh[nt][1], bl[nt][1]);
                }
            }
#pragma unroll
            for (int mt = 0; mt < 4; mt++)
#pragma unroll
                for (int nt = 0; nt < 4; nt++)
                    mma_tf32(c[mt][nt][0], c[mt][nt][1], c[mt][nt][2], c[mt][nt][3],
                             ah[mt][0], ah[mt][1], ah[mt][2], ah[mt][3],
                             bh[nt][0], bh[nt][1]);
#pragma unroll
            for (int mt = 0; mt < 4; mt++)
#pragma unroll
                for (int nt = 0; nt < 4; nt++)
                    mma_tf32(c[mt][nt][0], c[mt][nt][1], c[mt][nt][2], c[mt][nt][3],
                             ah[mt][0], ah[mt][1], ah[mt][2], ah[mt][3],
                             bl[nt][0], bl[nt][1]);
#pragma unroll
            for (int mt = 0; mt < 4; mt++)
#pragma unroll
                for (int nt = 0; nt < 4; nt++)
                    mma_tf32(c[mt][nt][0], c[mt][nt][1], c[mt][nt][2], c[mt][nt][3],
                             al[mt][0], al[mt][1], al[mt][2], al[mt][3],
                             bh[nt][0], bh[nt][1]);
        }

        if (more) {
            cp_wait0();
            __syncthreads();
            buf ^= 1;
        }
    }

    // ---- epilogue ----
#pragma unroll
    for (int mt = 0; mt < 4; mt++) {
        const int gr0 = brow * BM + mBase + mt * 16 + grp;
#pragma unroll
        for (int nt = 0; nt < 4; nt++) {
            const int gc = bcol * BN + nBase + nt * 8 + kA * 2;
#pragma unroll
            for (int h = 0; h < 2; h++) {
                const int gr = gr0 + h * 8;
                float v0 = c[mt][nt][h * 2 + 0];
                float v1 = c[mt][nt][h * 2 + 1];
                if (EPI == 4) {
                    const int half = N >> 1;
                    const bool ok0 = (gr < half) ? (gc < half) : (gc <= gr);
                    const bool ok1 = (gr < half) ? (gc + 1 < half) : (gc + 1 <= gr);
                    v0 = alpha * v0 + (ok0 ? 0.f : -1000.f);
                    v1 = alpha * v1 + (ok1 ? 0.f : -1000.f);
                } else if (EPI != 0) {
                    v0 += bias[gc];
                    v1 += bias[gc + 1];
                    if (EPI == 2) {
                        v0 = 0.5f * v0 * (1.f + erff(v0 * 0.70710678118654752f));
                        v1 = 0.5f * v1 * (1.f + erff(v1 * 0.70710678118654752f));
                    }
                    if (EPI == 3) {
                        const float* rr = resid + (long)bz * sR + (long)gr * ldc + gc;
                        v0 += rr[0];
                        v1 += rr[1];
                    }
                }
                *reinterpret_cast<float2*>(&C[(long)gr * ldc + gc]) = make_float2(v0, v1);
            }
        }
    }
}

// Row softmax over N=2048, one block (256 thr, 8 elems/thr) per row.
__global__ __launch_bounds__(256)
void softmax_k(float* __restrict__ S)
{
    const int N = 2048;
    float* p = S + (size_t)blockIdx.x * N;
    const int t = threadIdx.x;

    float v[8];
    float mx = -1e30f;
#pragma unroll
    for (int u = 0; u < 8; u++) {
        v[u] = p[t + 256 * u];
        mx = fmaxf(mx, v[u]);
    }
    __shared__ float red[8];
#pragma unroll
    for (int o = 16; o > 0; o >>= 1) mx = fmaxf(mx, __shfl_xor_sync(0xffffffffu, mx, o));
    if ((t & 31) == 0) red[t >> 5] = mx;
    __syncthreads();
    mx = red[0];
#pragma unroll
    for (int i = 1; i < 8; i++) mx = fmaxf(mx, red[i]);

    float s = 0.f;
#pragma unroll
    for (int u = 0; u < 8; u++) {
        v[u] = __expf(v[u] - mx);
        s += v[u];
    }
#pragma unroll
    for (int o = 16; o > 0; o >>= 1) s += __shfl_xor_sync(0xffffffffu, s, o);
    __syncthreads();
    if ((t & 31) == 0) red[t >> 5] = s;
    __syncthreads();
    s = red[0];
#pragma unroll
    for (int i = 1; i < 8; i++) s += red[i];

    const float inv = 1.f / s;
#pragma unroll
    for (int u = 0; u < 8; u++) p[t + 256 * u] = v[u] * inv;
}

// LayerNorm over C=512, one block (128 thr, float4/thr) per row.
__global__ __launch_bounds__(128)
void ln_k(const float* __restrict__ X, const float* __restrict__ g,
          const float* __restrict__ b, float* __restrict__ Y)
{
    const int C = 512;
    const float* x = X + (size_t)blockIdx.x * C;
    float* y = Y + (size_t)blockIdx.x * C;
    const int t = threadIdx.x;

    float4 v = *reinterpret_cast<const float4*>(x + t * 4);
    float s = v.x + v.y + v.z + v.w;

    __shared__ float red[4];
#pragma unroll
    for (int o = 16; o > 0; o >>= 1) s += __shfl_xor_sync(0xffffffffu, s, o);
    if ((t & 31) == 0) red[t >> 5] = s;
    __syncthreads();
    const float mean = (red[0] + red[1] + red[2] + red[3]) * (1.f / 512.f);

    const float dx = v.x - mean, dy = v.y - mean, dz = v.z - mean, dw = v.w - mean;
    float q = dx * dx + dy * dy + dz * dz + dw * dw;
#pragma unroll
    for (int o = 16; o > 0; o >>= 1) q += __shfl_xor_sync(0xffffffffu, q, o);
    __syncthreads();
    if ((t & 31) == 0) red[t >> 5] = q;
    __syncthreads();
    const float var = (red[0] + red[1] + red[2] + red[3]) * (1.f / 512.f);
    const float rstd = rsqrtf(var + 1e-5f);

    float4 gg = *reinterpret_cast<const float4*>(g + t * 4);
    float4 bb = *reinterpret_cast<const float4*>(b + t * 4);
    float4 o;
    o.x = dx * rstd * gg.x + bb.x;
    o.y = dy * rstd * gg.y + bb.y;
    o.z = dz * rstd * gg.z + bb.z;
    o.w = dw * rstd * gg.w + bb.w;
    *reinterpret_cast<float4*>(y + t * 4) = o;
}

extern "C" void kernel_launch(void* const* d_in, const int* in_sizes, int n_in,
                              void* d_out, int out_size)
{
    const float* x_in  = (const float*)d_in[0];
    const float* qkv_w = (const float*)d_in[1];
    const float* qkv_b = (const float*)d_in[2];
    const float* ln_g  = (const float*)d_in[3];
    const float* ln_b  = (const float*)d_in[4];
    const float* fc1_w = (const float*)d_in[5];
    const float* fc1_b = (const float*)d_in[6];
    const float* fc2_w = (const float*)d_in[7];
    const float* fc2_b = (const float*)d_in[8];
    float* x = (float*)d_out;

    float *qkv, *S, *y, *h;
    cudaGetSymbolAddress((void**)&qkv, g_qkv);
    cudaGetSymbolAddress((void**)&S,   g_s);
    cudaGetSymbolAddress((void**)&y,   g_y);
    cudaGetSymbolAddress((void**)&h,   g_h);

    const int Bn = 8, Nn = 2048, Cn = 512;
    const long xs = (long)Nn * Cn;
    const float scale = 0.044194173824159216f;  // 512^-0.5

    cudaMemcpyAsync(x, x_in, sizeof(float) * Bn * Nn * Cn, cudaMemcpyDeviceToDevice);

    for (int l = 0; l < 5; l++) {
        // qkv = x @ qkv_w[l] + qkv_b[l]                     (2048x1536x512)
        gemm_k<1, false, false><<<dim3(12, 16, 8), 256>>>(
            x, qkv_w + (long)l * Cn * 3 * Cn, qkv_b + l * 3 * Cn, nullptr, qkv,
            Nn, 3 * Cn, Cn, Cn, 3 * Cn, 3 * Cn, xs, 0, (long)Nn * 3 * Cn, 0, 1.f);

        // S = scale * q @ k^T + mask bias                   (2048x2048x512)
        gemm_k<4, true, false><<<dim3(16, 16, 8), 256>>>(
            qkv, qkv + Cn, nullptr, nullptr, S,
            Nn, Nn, Cn, 3 * Cn, 3 * Cn, Nn,
            (long)Nn * 3 * Cn, (long)Nn * 3 * Cn, (long)Nn * Nn, 0, scale);

        // P = softmax(S) row-wise
        softmax_k<<<Bn * Nn, 256>>>(S);

        // x = P @ v   (K truncated per block row)           (2048x512x<=2048)
        gemm_k<0, false, true><<<dim3(4, 16, 8), 256>>>(
            S, qkv + 2 * Cn, nullptr, nullptr, x,
            Nn, Cn, Nn, Nn, 3 * Cn, Cn,
            (long)Nn * Nn, (long)Nn * 3 * Cn, xs, 0, 1.f);

        // y = layernorm(x, g, b)
        ln_k<<<Bn * Nn, 128>>>(x, ln_g + l * Cn, ln_b + l * Cn, y);

        // h = gelu(y @ fc1_w[l] + fc1_b[l])                 (2048x1024x512)
        gemm_k<2, false, false><<<dim3(8, 16, 8), 256>>>(
            y, fc1_w + (long)l * Cn * 2 * Cn, fc1_b + l * 2 * Cn, nullptr, h,
            Nn, 2 * Cn, Cn, Cn, 2 * Cn, 2 * Cn, xs, 0, (long)Nn * 2 * Cn, 0, 1.f);

        // x = x + h @ fc2_w[l] + fc2_b[l]                   (2048x512x1024)
        gemm_k<3, false, false><<<dim3(4, 16, 8), 256>>>(
            h, fc2_w + (long)l * 2 * Cn * Cn, fc2_b + l * Cn, x, x,
            Nn, Cn, 2 * Cn, 2 * Cn, Cn, Cn, (long)Nn * 2 * Cn, 0, xs, xs, 1.f);
    }
}

// round 11
// speedup vs baseline: 2.4852x; 1.5617x over previous
#include <cuda_runtime.h>
#include <math.h>

// ---------------------------------------------------------------------------
// maskedContextModel: B=8, N=2048, C=512, L=5
// Round 10: 3-term bf16 split GEMM (ah*bh + ah*bl + al*bh, fp32 accum) on
// mma.m16n8k16.bf16 — half the MMA issue and 2x tensor rate vs 3xTF32.
// fp32 smem tiles, float2 fragment feed, cp.async double buffer, 2 CTA/SM.
// Mask block-skip + K-truncation retained.
// ---------------------------------------------------------------------------

__device__ float g_qkv[(size_t)8 * 2048 * 1536];
__device__ float g_s  [(size_t)8 * 2048 * 2048];
__device__ float g_y  [(size_t)8 * 2048 * 512];
__device__ float g_h  [(size_t)8 * 2048 * 1024];

// split two fp32 into packed bf16x2 hi and lo (lo = rn residual), x in low half
__device__ __forceinline__ void split2(float x, float y, unsigned& hi2, unsigned& lo2) {
    asm("cvt.rn.bf16x2.f32 %0, %1, %2;" : "=r"(hi2) : "f"(y), "f"(x));
    float hx = __uint_as_float(hi2 << 16);
    float hy = __uint_as_float(hi2 & 0xFFFF0000u);
    float lx = x - hx;
    float ly = y - hy;
    asm("cvt.rn.bf16x2.f32 %0, %1, %2;" : "=r"(lo2) : "f"(ly), "f"(lx));
}

__device__ __forceinline__ void mma_bf16(float& c0, float& c1, float& c2, float& c3,
                                         unsigned a0, unsigned a1, unsigned a2, unsigned a3,
                                         unsigned b0, unsigned b1) {
    asm volatile(
        "mma.sync.aligned.m16n8k16.row.col.f32.bf16.bf16.f32 "
        "{%0,%1,%2,%3}, {%4,%5,%6,%7}, {%8,%9}, {%0,%1,%2,%3};"
        : "+f"(c0), "+f"(c1), "+f"(c2), "+f"(c3)
        : "r"(a0), "r"(a1), "r"(a2), "r"(a3), "r"(b0), "r"(b1));
}

__device__ __forceinline__ void cp16(float* s, const float* g) {
    unsigned sa = (unsigned)__cvta_generic_to_shared(s);
    asm volatile("cp.async.cg.shared.global [%0], [%1], 16;" :: "r"(sa), "l"(g));
}
__device__ __forceinline__ void cp_commit() { asm volatile("cp.async.commit_group;"); }
__device__ __forceinline__ void cp_wait0()  { asm volatile("cp.async.wait_group 0;" ::: "memory"); }

// A / TB-B tile: [128 rows][16 k] fp32, row pitch 20
// NN-B tile:     [16 k][128 n] fp32, row pitch 136
#define APITCH 20
#define BPITCH 136
#define TILEF  2560

// EPI: 0=none, 1=+bias, 2=gelu(+bias), 3=+bias+residual, 4=attn mask
// TB: B is [N x K] row-major (k-contiguous); MASKK: P@V K truncation
template <int EPI, bool TB, bool MASKK>
__global__ __launch_bounds__(256, 2)
void gemm_k(const float* __restrict__ A, const float* __restrict__ B,
            const float* __restrict__ bias, const float* resid, float* C,
            int M, int N, int K, int lda, int ldb, int ldc,
            long sA, long sB, long sC, long sR, float alpha)
{
    const int BM = 128, BN = 128, BK = 16;
    __shared__ float As[2][TILEF];
    __shared__ float Bs[2][TILEF];

    const int bz   = blockIdx.z;
    const int tid  = threadIdx.x;
    const int brow = blockIdx.y, bcol = blockIdx.x;

    const int lane  = tid & 31;
    const int warp  = tid >> 5;
    const int warpM = warp & 1;
    const int warpN = warp >> 1;
    const int kA    = lane & 3;
    const int grp   = lane >> 2;
    const int mBase = warpM * 64;
    const int nBase = warpN * 32;

    C += (long)bz * sC;

    if (EPI == 4) {
        if ((bcol >= 8 || brow >= 8) && bcol > brow) {
            float2 mk = make_float2(-1000.f, -1000.f);
#pragma unroll
            for (int mt = 0; mt < 4; mt++) {
                const long gr0 = brow * BM + mBase + mt * 16 + grp;
#pragma unroll
                for (int nt = 0; nt < 4; nt++) {
                    const int gc = bcol * BN + nBase + nt * 8 + kA * 2;
                    *reinterpret_cast<float2*>(&C[gr0 * ldc + gc]) = mk;
                    *reinterpret_cast<float2*>(&C[(gr0 + 8) * ldc + gc]) = mk;
                }
            }
            return;
        }
    }

    A += (long)bz * sA;
    B += (long)bz * sB;

    int Keff = K;
    if (MASKK) Keff = (brow < 8) ? 1024 : (brow + 1) * 128;

    // ---- loader coordinates ----
    const int aRow   = tid >> 1;
    const int aChunk = (tid & 1) * 8;
    const float* Ab  = A + (long)(brow * BM + aRow) * lda + aChunk;
    float* AsDst0 = &As[0][aRow * APITCH + aChunk];
    float* AsDst1 = &As[1][aRow * APITCH + aChunk];

    const int bKr  = tid >> 4;
    const int bNc8 = (tid & 15) * 8;
    const float* BbNN = B + bcol * BN + (long)bKr * ldb + bNc8;
    const float* BbTB = B + (long)(bcol * BN + aRow) * ldb + aChunk;
    float* BsDstNN0 = &Bs[0][bKr * BPITCH + bNc8];
    float* BsDstNN1 = &Bs[1][bKr * BPITCH + bNc8];
    float* BsDstTB0 = &Bs[0][aRow * APITCH + aChunk];
    float* BsDstTB1 = &Bs[1][aRow * APITCH + aChunk];

    float c[4][4][4];
#pragma unroll
    for (int mt = 0; mt < 4; mt++)
#pragma unroll
        for (int nt = 0; nt < 4; nt++)
#pragma unroll
            for (int i = 0; i < 4; i++) c[mt][nt][i] = 0.f;

    // ---- preload stage 0 ----
    {
        cp16(AsDst0, Ab);
        cp16(AsDst0 + 4, Ab + 4);
        if (TB) {
            cp16(BsDstTB0, BbTB);
            cp16(BsDstTB0 + 4, BbTB + 4);
        } else {
            cp16(BsDstNN0, BbNN);
            cp16(BsDstNN0 + 4, BbNN + 4);
        }
        cp_commit();
        cp_wait0();
    }
    __syncthreads();

    const int nstages = Keff / BK;
    int buf = 0;
    for (int t = 0; t < nstages; ++t) {
        const bool more = (t + 1) < nstages;
        if (more) {
            const int k0 = (t + 1) * BK;
            float* ad = buf ? AsDst0 : AsDst1;
            cp16(ad, Ab + k0);
            cp16(ad + 4, Ab + k0 + 4);
            if (TB) {
                float* bd = buf ? BsDstTB0 : BsDstTB1;
                cp16(bd, BbTB + k0);
                cp16(bd + 4, BbTB + k0 + 4);
            } else {
                float* bd = buf ? BsDstNN0 : BsDstNN1;
                cp16(bd, BbNN + (long)k0 * ldb);
                cp16(bd + 4, BbNN + (long)k0 * ldb + 4);
            }
            cp_commit();
        }

        const float* Abuf = As[buf];
        const float* Bbuf = Bs[buf];

        // ---- fragments: one k16 slab ----
        unsigned ah[4][4], al[4][4];
#pragma unroll
        for (int mt = 0; mt < 4; mt++) {
            const float* ar = &Abuf[(mBase + mt * 16 + grp) * APITCH + 2 * kA];
            float2 p0 = *reinterpret_cast<const float2*>(ar);
            float2 p1 = *reinterpret_cast<const float2*>(ar + 8 * APITCH);
            float2 p2 = *reinterpret_cast<const float2*>(ar + 8);
            float2 p3 = *reinterpret_cast<const float2*>(ar + 8 * APITCH + 8);
            split2(p0.x, p0.y, ah[mt][0], al[mt][0]);
            split2(p1.x, p1.y, ah[mt][1], al[mt][1]);
            split2(p2.x, p2.y, ah[mt][2], al[mt][2]);
            split2(p3.x, p3.y, ah[mt][3], al[mt][3]);
        }
        unsigned bh[4][2], bl[4][2];
#pragma unroll
        for (int nt = 0; nt < 4; nt++) {
            if (TB) {
                const float* br = &Bbuf[(nBase + nt * 8 + grp) * APITCH + 2 * kA];
                float2 q0 = *reinterpret_cast<const float2*>(br);
                float2 q1 = *reinterpret_cast<const float2*>(br + 8);
                split2(q0.x, q0.y, bh[nt][0], bl[nt][0]);
                split2(q1.x, q1.y, bh[nt][1], bl[nt][1]);
            } else {
                const float* br = &Bbuf[(2 * kA) * BPITCH + nBase + nt * 8 + grp];
                float x0 = br[0];
                float x1 = br[BPITCH];
                float x2 = br[8 * BPITCH];
                float x3 = br[9 * BPITCH];
                split2(x0, x1, bh[nt][0], bl[nt][0]);
                split2(x2, x3, bh[nt][1], bl[nt][1]);
            }
        }

#pragma unroll
        for (int mt = 0; mt < 4; mt++)
#pragma unroll
            for (int nt = 0; nt < 4; nt++)
                mma_bf16(c[mt][nt][0], c[mt][nt][1], c[mt][nt][2], c[mt][nt][3],
                         ah[mt][0], ah[mt][1], ah[mt][2], ah[mt][3],
                         bh[nt][0], bh[nt][1]);
#pragma unroll
        for (int mt = 0; mt < 4; mt++)
#pragma unroll
            for (int nt = 0; nt < 4; nt++)
                mma_bf16(c[mt][nt][0], c[mt][nt][1], c[mt][nt][2], c[mt][nt][3],
                         ah[mt][0], ah[mt][1], ah[mt][2], ah[mt][3],
                         bl[nt][0], bl[nt][1]);
#pragma unroll
        for (int mt = 0; mt < 4; mt++)
#pragma unroll
            for (int nt = 0; nt < 4; nt++)
                mma_bf16(c[mt][nt][0], c[mt][nt][1], c[mt][nt][2], c[mt][nt][3],
                         al[mt][0], al[mt][1], al[mt][2], al[mt][3],
                         bh[nt][0], bh[nt][1]);

        if (more) {
            cp_wait0();
            __syncthreads();
            buf ^= 1;
        }
    }

    // ---- epilogue ----
#pragma unroll
    for (int mt = 0; mt < 4; mt++) {
        const int gr0 = brow * BM + mBase + mt * 16 + grp;
#pragma unroll
        for (int nt = 0; nt < 4; nt++) {
            const int gc = bcol * BN + nBase + nt * 8 + kA * 2;
#pragma unroll
            for (int h = 0; h < 2; h++) {
                const int gr = gr0 + h * 8;
                float v0 = c[mt][nt][h * 2 + 0];
                float v1 = c[mt][nt][h * 2 + 1];
                if (EPI == 4) {
                    const int half = N >> 1;
                    const bool ok0 = (gr < half) ? (gc < half) : (gc <= gr);
                    const bool ok1 = (gr < half) ? (gc + 1 < half) : (gc + 1 <= gr);
                    v0 = alpha * v0 + (ok0 ? 0.f : -1000.f);
                    v1 = alpha * v1 + (ok1 ? 0.f : -1000.f);
                } else if (EPI != 0) {
                    v0 += bias[gc];
                    v1 += bias[gc + 1];
                    if (EPI == 2) {
                        v0 = 0.5f * v0 * (1.f + erff(v0 * 0.70710678118654752f));
                        v1 = 0.5f * v1 * (1.f + erff(v1 * 0.70710678118654752f));
                    }
                    if (EPI == 3) {
                        const float* rr = resid + (long)bz * sR + (long)gr * ldc + gc;
                        v0 += rr[0];
                        v1 += rr[1];
                    }
                }
                *reinterpret_cast<float2*>(&C[(long)gr * ldc + gc]) = make_float2(v0, v1);
            }
        }
    }
}

// Row softmax over N=2048, one block (256 thr, 8 elems/thr) per row.
__global__ __launch_bounds__(256)
void softmax_k(float* __restrict__ S)
{
    const int N = 2048;
    float* p = S + (size_t)blockIdx.x * N;
    const int t = threadIdx.x;

    float v[8];
    float mx = -1e30f;
#pragma unroll
    for (int u = 0; u < 8; u++) {
        v[u] = p[t + 256 * u];
        mx = fmaxf(mx, v[u]);
    }
    __shared__ float red[8];
#pragma unroll
    for (int o = 16; o > 0; o >>= 1) mx = fmaxf(mx, __shfl_xor_sync(0xffffffffu, mx, o));
    if ((t & 31) == 0) red[t >> 5] = mx;
    __syncthreads();
    mx = red[0];
#pragma unroll
    for (int i = 1; i < 8; i++) mx = fmaxf(mx, red[i]);

    float s = 0.f;
#pragma unroll
    for (int u = 0; u < 8; u++) {
        v[u] = __expf(v[u] - mx);
        s += v[u];
    }
#pragma unroll
    for (int o = 16; o > 0; o >>= 1) s += __shfl_xor_sync(0xffffffffu, s, o);
    __syncthreads();
    if ((t & 31) == 0) red[t >> 5] = s;
    __syncthreads();
    s = red[0];
#pragma unroll
    for (int i = 1; i < 8; i++) s += red[i];

    const float inv = 1.f / s;
#pragma unroll
    for (int u = 0; u < 8; u++) p[t + 256 * u] = v[u] * inv;
}

// LayerNorm over C=512, one block (128 thr, float4/thr) per row.
__global__ __launch_bounds__(128)
void ln_k(const float* __restrict__ X, const float* __restrict__ g,
          const float* __restrict__ b, float* __restrict__ Y)
{
    const int C = 512;
    const float* x = X + (size_t)blockIdx.x * C;
    float* y = Y + (size_t)blockIdx.x * C;
    const int t = threadIdx.x;

    float4 v = *reinterpret_cast<const float4*>(x + t * 4);
    float s = v.x + v.y + v.z + v.w;

    __shared__ float red[4];
#pragma unroll
    for (int o = 16; o > 0; o >>= 1) s += __shfl_xor_sync(0xffffffffu, s, o);
    if ((t & 31) == 0) red[t >> 5] = s;
    __syncthreads();
    const float mean = (red[0] + red[1] + red[2] + red[3]) * (1.f / 512.f);

    const float dx = v.x - mean, dy = v.y - mean, dz = v.z - mean, dw = v.w - mean;
    float q = dx * dx + dy * dy + dz * dz + dw * dw;
#pragma unroll
    for (int o = 16; o > 0; o >>= 1) q += __shfl_xor_sync(0xffffffffu, q, o);
    __syncthreads();
    if ((t & 31) == 0) red[t >> 5] = q;
    __syncthreads();
    const float var = (red[0] + red[1] + red[2] + red[3]) * (1.f / 512.f);
    const float rstd = rsqrtf(var + 1e-5f);

    float4 gg = *reinterpret_cast<const float4*>(g + t * 4);
    float4 bb = *reinterpret_cast<const float4*>(b + t * 4);
    float4 o;
    o.x = dx * rstd * gg.x + bb.x;
    o.y = dy * rstd * gg.y + bb.y;
    o.z = dz * rstd * gg.z + bb.z;
    o.w = dw * rstd * gg.w + bb.w;
    *reinterpret_cast<float4*>(y + t * 4) = o;
}

extern "C" void kernel_launch(void* const* d_in, const int* in_sizes, int n_in,
                              void* d_out, int out_size)
{
    const float* x_in  = (const float*)d_in[0];
    const float* qkv_w = (const float*)d_in[1];
    const float* qkv_b = (const float*)d_in[2];
    const float* ln_g  = (const float*)d_in[3];
    const float* ln_b  = (const float*)d_in[4];
    const float* fc1_w = (const float*)d_in[5];
    const float* fc1_b = (const float*)d_in[6];
    const float* fc2_w = (const float*)d_in[7];
    const float* fc2_b = (const float*)d_in[8];
    float* x = (float*)d_out;

    float *qkv, *S, *y, *h;
    cudaGetSymbolAddress((void**)&qkv, g_qkv);
    cudaGetSymbolAddress((void**)&S,   g_s);
    cudaGetSymbolAddress((void**)&y,   g_y);
    cudaGetSymbolAddress((void**)&h,   g_h);

    const int Bn = 8, Nn = 2048, Cn = 512;
    const long xs = (long)Nn * Cn;
    const float scale = 0.044194173824159216f;  // 512^-0.5

    cudaMemcpyAsync(x, x_in, sizeof(float) * Bn * Nn * Cn, cudaMemcpyDeviceToDevice);

    for (int l = 0; l < 5; l++) {
        // qkv = x @ qkv_w[l] + qkv_b[l]                     (2048x1536x512)
        gemm_k<1, false, false><<<dim3(12, 16, 8), 256>>>(
            x, qkv_w + (long)l * Cn * 3 * Cn, qkv_b + l * 3 * Cn, nullptr, qkv,
            Nn, 3 * Cn, Cn, Cn, 3 * Cn, 3 * Cn, xs, 0, (long)Nn * 3 * Cn, 0, 1.f);

        // S = scale * q @ k^T + mask bias                   (2048x2048x512)
        gemm_k<4, true, false><<<dim3(16, 16, 8), 256>>>(
            qkv, qkv + Cn, nullptr, nullptr, S,
            Nn, Nn, Cn, 3 * Cn, 3 * Cn, Nn,
            (long)Nn * 3 * Cn, (long)Nn * 3 * Cn, (long)Nn * Nn, 0, scale);

        // P = softmax(S) row-wise
        softmax_k<<<Bn * Nn, 256>>>(S);

        // x = P @ v   (K truncated per block row)           (2048x512x<=2048)
        gemm_k<0, false, true><<<dim3(4, 16, 8), 256>>>(
            S, qkv + 2 * Cn, nullptr, nullptr, x,
            Nn, Cn, Nn, Nn, 3 * Cn, Cn,
            (long)Nn * Nn, (long)Nn * 3 * Cn, xs, 0, 1.f);

        // y = layernorm(x, g, b)
        ln_k<<<Bn * Nn, 128>>>(x, ln_g + l * Cn, ln_b + l * Cn, y);

        // h = gelu(y @ fc1_w[l] + fc1_b[l])                 (2048x1024x512)
        gemm_k<2, false, false><<<dim3(8, 16, 8), 256>>>(
            y, fc1_w + (long)l * Cn * 2 * Cn, fc1_b + l * 2 * Cn, nullptr, h,
            Nn, 2 * Cn, Cn, Cn, 2 * Cn, 2 * Cn, xs, 0, (long)Nn * 2 * Cn, 0, 1.f);

        // x = x + h @ fc2_w[l] + fc2_b[l]                   (2048x512x1024)
        gemm_k<3, false, false><<<dim3(4, 16, 8), 256>>>(
            h, fc2_w + (long)l * 2 * Cn * Cn, fc2_b + l * Cn, x, x,
            Nn, Cn, 2 * Cn, 2 * Cn, Cn, Cn, (long)Nn * 2 * Cn, 0, xs, xs, 1.f);
    }
}

// round 13
// speedup vs baseline: 2.6384x; 1.0617x over previous
#include <cuda_runtime.h>
#include <cuda_bf16.h>
#include <math.h>

// ---------------------------------------------------------------------------
// maskedContextModel: B=8, N=2048, C=512, L=5
// Round 11: pre-split bf16 hi/lo operands in gmem; GEMM = pure bf16 MMA
// (3-term: ah*bh + ah*bl + al*bh, fp32 accum), cp.async BK=32 double buffer,
// conflict-free LDS fragment feed, epilogue-fused splits everywhere.
// ---------------------------------------------------------------------------

#define NB  8
#define NN_ 2048
#define CC  512

__device__ float g_S[(size_t)NB * NN_ * NN_];

__device__ __nv_bfloat16 g_xh[(size_t)NB * NN_ * CC],  g_xl[(size_t)NB * NN_ * CC];
__device__ __nv_bfloat16 g_qh[(size_t)NB * NN_ * CC],  g_ql[(size_t)NB * NN_ * CC];
__device__ __nv_bfloat16 g_kh[(size_t)NB * NN_ * CC],  g_kl[(size_t)NB * NN_ * CC];
__device__ __nv_bfloat16 g_vth[(size_t)NB * CC * NN_], g_vtl[(size_t)NB * CC * NN_];
__device__ __nv_bfloat16 g_Ph[(size_t)NB * NN_ * NN_], g_Pl[(size_t)NB * NN_ * NN_];
__device__ __nv_bfloat16 g_yh[(size_t)NB * NN_ * CC],  g_yl[(size_t)NB * NN_ * CC];
__device__ __nv_bfloat16 g_hh[(size_t)NB * NN_ * 1024], g_hl[(size_t)NB * NN_ * 1024];

__device__ __nv_bfloat16 g_wqh[(size_t)5 * 1536 * 512], g_wql[(size_t)5 * 1536 * 512];
__device__ __nv_bfloat16 g_w1h[(size_t)5 * 1024 * 512], g_w1l[(size_t)5 * 1024 * 512];
__device__ __nv_bfloat16 g_w2h[(size_t)5 * 512 * 1024], g_w2l[(size_t)5 * 512 * 1024];

__device__ __forceinline__ void split_bf(float v, __nv_bfloat16& h, __nv_bfloat16& l) {
    h = __float2bfloat16_rn(v);
    l = __float2bfloat16_rn(v - __bfloat162float(h));
}
__device__ __forceinline__ unsigned pack2(__nv_bfloat16 a, __nv_bfloat16 b) {
    unsigned ua = *reinterpret_cast<unsigned short*>(&a);
    unsigned ub = *reinterpret_cast<unsigned short*>(&b);
    return ua | (ub << 16);
}

__device__ __forceinline__ void mma_bf16(float& c0, float& c1, float& c2, float& c3,
                                         unsigned a0, unsigned a1, unsigned a2, unsigned a3,
                                         unsigned b0, unsigned b1) {
    asm volatile(
        "mma.sync.aligned.m16n8k16.row.col.f32.bf16.bf16.f32 "
        "{%0,%1,%2,%3}, {%4,%5,%6,%7}, {%8,%9}, {%0,%1,%2,%3};"
        : "+f"(c0), "+f"(c1), "+f"(c2), "+f"(c3)
        : "r"(a0), "r"(a1), "r"(a2), "r"(a3), "r"(b0), "r"(b1));
}

__device__ __forceinline__ void cp16(unsigned* s, const __nv_bfloat16* g) {
    unsigned sa = (unsigned)__cvta_generic_to_shared(s);
    asm volatile("cp.async.cg.shared.global [%0], [%1], 16;" :: "r"(sa), "l"(g));
}
__device__ __forceinline__ void cp_commit() { asm volatile("cp.async.commit_group;"); }
__device__ __forceinline__ void cp_wait0()  { asm volatile("cp.async.wait_group 0;" ::: "memory"); }

#define PW    20            // words (uint) per tile row = 40 halves (32 used + pad)
#define TILEW (128 * PW)    // 2560 words per plane-buffer
static const int GEMM_SMEM = 8 * TILEW * 4;   // 81920 B

// EPI: 0 = PV (plain fp32 out), 1 = QKV (bias + split q/k/vT),
//      2 = fc1 (bias+gelu -> split h), 3 = fc2 (bias+resid -> fp32 x + split x),
//      4 = S (alpha + mask -> fp32)
template <int EPI, bool MASKK>
__global__ __launch_bounds__(256, 2)
void gemm_bf16(const __nv_bfloat16* __restrict__ Ah, const __nv_bfloat16* __restrict__ Al,
               const __nv_bfloat16* __restrict__ Bh, const __nv_bfloat16* __restrict__ Bl,
               const float* __restrict__ bias, const float* __restrict__ resid,
               float* outF,
               int M, int N, int K, int lda, int ldb, int ldc,
               long sA, long sB, long sC, float alpha)
{
    extern __shared__ unsigned sm[];

    const int bz   = blockIdx.z;
    const int tid  = threadIdx.x;
    const int brow = blockIdx.y, bcol = blockIdx.x;

    const int lane  = tid & 31;
    const int warp  = tid >> 5;
    const int warpM = warp & 1;
    const int warpN = warp >> 1;
    const int kA    = lane & 3;
    const int grp   = lane >> 2;
    const int mBase = warpM * 64;
    const int nBase = warpN * 32;

    if (EPI == 0 || EPI == 3 || EPI == 4) outF += (long)bz * sC;

    // ---- fully masked S-tile: fill -1000, skip ----
    if (EPI == 4) {
        if ((bcol >= 8 || brow >= 8) && bcol > brow) {
            float2 mk = make_float2(-1000.f, -1000.f);
#pragma unroll
            for (int mt = 0; mt < 4; mt++) {
                const long gr0 = brow * 128 + mBase + mt * 16 + grp;
#pragma unroll
                for (int nt = 0; nt < 4; nt++) {
                    const int gc = bcol * 128 + nBase + nt * 8 + kA * 2;
                    *reinterpret_cast<float2*>(&outF[gr0 * ldc + gc]) = mk;
                    *reinterpret_cast<float2*>(&outF[(gr0 + 8) * ldc + gc]) = mk;
                }
            }
            return;
        }
    }

    Ah += (long)bz * sA;  Al += (long)bz * sA;
    Bh += (long)bz * sB;  Bl += (long)bz * sB;

    int Keff = K;
    if (MASKK) Keff = (brow < 8) ? 1024 : (brow + 1) * 128;

    // ---- loader coords: thread -> (row, 32B chunk) of each 128x32 tile ----
    const int row = tid >> 1;
    const int hf  = tid & 1;
    const __nv_bfloat16* agH = Ah + (long)(brow * 128 + row) * lda + hf * 16;
    const __nv_bfloat16* agL = Al + (long)(brow * 128 + row) * lda + hf * 16;
    const __nv_bfloat16* bgH = Bh + (long)(bcol * 128 + row) * ldb + hf * 16;
    const __nv_bfloat16* bgL = Bl + (long)(bcol * 128 + row) * ldb + hf * 16;
    const int dstw = row * PW + hf * 8;

    float c[4][4][4];
#pragma unroll
    for (int mt = 0; mt < 4; mt++)
#pragma unroll
        for (int nt = 0; nt < 4; nt++)
#pragma unroll
            for (int i = 0; i < 4; i++) c[mt][nt][i] = 0.f;

    // ---- preload stage 0 ----
    {
        cp16(sm + 0 * TILEW + dstw, agH);      cp16(sm + 0 * TILEW + dstw + 4, agH + 8);
        cp16(sm + 2 * TILEW + dstw, agL);      cp16(sm + 2 * TILEW + dstw + 4, agL + 8);
        cp16(sm + 4 * TILEW + dstw, bgH);      cp16(sm + 4 * TILEW + dstw + 4, bgH + 8);
        cp16(sm + 6 * TILEW + dstw, bgL);      cp16(sm + 6 * TILEW + dstw + 4, bgL + 8);
        cp_commit();
        cp_wait0();
    }
    __syncthreads();

    const int nstages = Keff >> 5;      // BK = 32
    int buf = 0;
    for (int t = 0; t < nstages; ++t) {
        const bool more = (t + 1) < nstages;
        if (more) {
            const int k0 = (t + 1) * 32;
            const int nb = buf ^ 1;
            cp16(sm + nb * TILEW + dstw, agH + k0);
            cp16(sm + nb * TILEW + dstw + 4, agH + k0 + 8);
            cp16(sm + (2 + nb) * TILEW + dstw, agL + k0);
            cp16(sm + (2 + nb) * TILEW + dstw + 4, agL + k0 + 8);
            cp16(sm + (4 + nb) * TILEW + dstw, bgH + k0);
            cp16(sm + (4 + nb) * TILEW + dstw + 4, bgH + k0 + 8);
            cp16(sm + (6 + nb) * TILEW + dstw, bgL + k0);
            cp16(sm + (6 + nb) * TILEW + dstw + 4, bgL + k0 + 8);
            cp_commit();
        }

        const unsigned* AHb = sm + buf * TILEW;
        const unsigned* ALb = sm + (2 + buf) * TILEW;
        const unsigned* BHb = sm + (4 + buf) * TILEW;
        const unsigned* BLb = sm + (6 + buf) * TILEW;

#pragma unroll
        for (int ks = 0; ks < 2; ks++) {
            const int W0 = ks * 8 + kA;
            unsigned ah[4][4], al[4][4];
#pragma unroll
            for (int mt = 0; mt < 4; mt++) {
                const int w = (mBase + mt * 16 + grp) * PW + W0;
                ah[mt][0] = AHb[w];
                ah[mt][1] = AHb[w + 8 * PW];
                ah[mt][2] = AHb[w + 4];
                ah[mt][3] = AHb[w + 8 * PW + 4];
                al[mt][0] = ALb[w];
                al[mt][1] = ALb[w + 8 * PW];
                al[mt][2] = ALb[w + 4];
                al[mt][3] = ALb[w + 8 * PW + 4];
            }
            unsigned bh[4][2], bl[4][2];
#pragma unroll
            for (int nt = 0; nt < 4; nt++) {
                const int w = (nBase + nt * 8 + grp) * PW + W0;
                bh[nt][0] = BHb[w];
                bh[nt][1] = BHb[w + 4];
                bl[nt][0] = BLb[w];
                bl[nt][1] = BLb[w + 4];
            }
#pragma unroll
            for (int mt = 0; mt < 4; mt++)
#pragma unroll
                for (int nt = 0; nt < 4; nt++)
                    mma_bf16(c[mt][nt][0], c[mt][nt][1], c[mt][nt][2], c[mt][nt][3],
                             ah[mt][0], ah[mt][1], ah[mt][2], ah[mt][3],
                             bh[nt][0], bh[nt][1]);
#pragma unroll
            for (int mt = 0; mt < 4; mt++)
#pragma unroll
                for (int nt = 0; nt < 4; nt++)
                    mma_bf16(c[mt][nt][0], c[mt][nt][1], c[mt][nt][2], c[mt][nt][3],
                             ah[mt][0], ah[mt][1], ah[mt][2], ah[mt][3],
                             bl[nt][0], bl[nt][1]);
#pragma unroll
            for (int mt = 0; mt < 4; mt++)
#pragma unroll
                for (int nt = 0; nt < 4; nt++)
                    mma_bf16(c[mt][nt][0], c[mt][nt][1], c[mt][nt][2], c[mt][nt][3],
                             al[mt][0], al[mt][1], al[mt][2], al[mt][3],
                             bh[nt][0], bh[nt][1]);
        }

        if (more) {
            cp_wait0();
            __syncthreads();
            buf ^= 1;
        }
    }

    // ---- epilogue ----
#pragma unroll
    for (int mt = 0; mt < 4; mt++) {
        const int gr0 = brow * 128 + mBase + mt * 16 + grp;
#pragma unroll
        for (int nt = 0; nt < 4; nt++) {
            const int gc = bcol * 128 + nBase + nt * 8 + kA * 2;
#pragma unroll
            for (int h = 0; h < 2; h++) {
                const int gr = gr0 + h * 8;
                float v0 = c[mt][nt][h * 2 + 0];
                float v1 = c[mt][nt][h * 2 + 1];

                if (EPI == 0) {
                    *reinterpret_cast<float2*>(&outF[(long)gr * ldc + gc]) = make_float2(v0, v1);
                } else if (EPI == 4) {
                    const int half = N >> 1;
                    const bool ok0 = (gr < half) ? (gc < half) : (gc <= gr);
                    const bool ok1 = (gr < half) ? (gc + 1 < half) : (gc + 1 <= gr);
                    v0 = alpha * v0 + (ok0 ? 0.f : -1000.f);
                    v1 = alpha * v1 + (ok1 ? 0.f : -1000.f);
                    *reinterpret_cast<float2*>(&outF[(long)gr * ldc + gc]) = make_float2(v0, v1);
                } else if (EPI == 1) {
                    v0 += bias[gc];
                    v1 += bias[gc + 1];
                    __nv_bfloat16 h0, l0, h1, l1;
                    split_bf(v0, h0, l0);
                    split_bf(v1, h1, l1);
                    const int seg = gc >> 9;
                    const int col = gc & 511;
                    if (seg == 0) {
                        const long idx = ((long)bz * NN_ + gr) * CC + col;
                        *reinterpret_cast<unsigned*>(&g_qh[idx]) = pack2(h0, h1);
                        *reinterpret_cast<unsigned*>(&g_ql[idx]) = pack2(l0, l1);
                    } else if (seg == 1) {
                        const long idx = ((long)bz * NN_ + gr) * CC + col;
                        *reinterpret_cast<unsigned*>(&g_kh[idx]) = pack2(h0, h1);
                        *reinterpret_cast<unsigned*>(&g_kl[idx]) = pack2(l0, l1);
                    } else {
                        const long i0 = ((long)bz * CC + col) * NN_ + gr;
                        const long i1 = ((long)bz * CC + col + 1) * NN_ + gr;
                        g_vth[i0] = h0; g_vtl[i0] = l0;
                        g_vth[i1] = h1; g_vtl[i1] = l1;
                    }
                } else if (EPI == 2) {
                    v0 += bias[gc];
                    v1 += bias[gc + 1];
                    v0 = 0.5f * v0 * (1.f + erff(v0 * 0.70710678118654752f));
                    v1 = 0.5f * v1 * (1.f + erff(v1 * 0.70710678118654752f));
                    __nv_bfloat16 h0, l0, h1, l1;
                    split_bf(v0, h0, l0);
                    split_bf(v1, h1, l1);
                    const long idx = (long)bz * sC + (long)gr * ldc + gc;
                    *reinterpret_cast<unsigned*>(&g_hh[idx]) = pack2(h0, h1);
                    *reinterpret_cast<unsigned*>(&g_hl[idx]) = pack2(l0, l1);
                } else {  // EPI == 3
                    const float* rr = resid + (long)bz * sC + (long)gr * ldc + gc;
                    v0 += bias[gc] + rr[0];
                    v1 += bias[gc + 1] + rr[1];
                    *reinterpret_cast<float2*>(&outF[(long)gr * ldc + gc]) = make_float2(v0, v1);
                    __nv_bfloat16 h0, l0, h1, l1;
                    split_bf(v0, h0, l0);
                    split_bf(v1, h1, l1);
                    const long idx = (long)bz * sC + (long)gr * ldc + gc;
                    *reinterpret_cast<unsigned*>(&g_xh[idx]) = pack2(h0, h1);
                    *reinterpret_cast<unsigned*>(&g_xl[idx]) = pack2(l0, l1);
                }
            }
        }
    }
}

// Weight transpose + bf16 hi/lo split: W [L][K][N] fp32 -> T [L][N][K] bf16 x2
__global__ void wtrans_k(const float* __restrict__ W,
                         __nv_bfloat16* __restrict__ Th, __nv_bfloat16* __restrict__ Tl,
                         int K, int N)
{
    __shared__ float t[32][33];
    const int n0 = blockIdx.x * 32, k0 = blockIdx.y * 32, l = blockIdx.z;
    const int tx = threadIdx.x, ty = threadIdx.y;
    const float* Wl = W + (long)l * K * N;
#pragma unroll
    for (int i = 0; i < 4; i++)
        t[ty + 8 * i][tx] = Wl[(long)(k0 + ty + 8 * i) * N + n0 + tx];
    __syncthreads();
    const long ob = (long)l * N * K;
#pragma unroll
    for (int i = 0; i < 4; i++) {
        const int n = n0 + ty + 8 * i;
        float v = t[tx][ty + 8 * i];
        __nv_bfloat16 h, lo;
        split_bf(v, h, lo);
        Th[ob + (long)n * K + k0 + tx] = h;
        Tl[ob + (long)n * K + k0 + tx] = lo;
    }
}

// Initial x -> bf16 hi/lo planes
__global__ void xcvt_k(const float* __restrict__ x,
                       __nv_bfloat16* __restrict__ Xh, __nv_bfloat16* __restrict__ Xl)
{
    const long i = (long)blockIdx.x * 256 + threadIdx.x;   // one float4 per thread
    float4 v = reinterpret_cast<const float4*>(x)[i];
    __nv_bfloat16 h0, l0, h1, l1, h2, l2, h3, l3;
    split_bf(v.x, h0, l0); split_bf(v.y, h1, l1);
    split_bf(v.z, h2, l2); split_bf(v.w, h3, l3);
    unsigned* ph = reinterpret_cast<unsigned*>(Xh) + i * 2;
    unsigned* pl = reinterpret_cast<unsigned*>(Xl) + i * 2;
    ph[0] = pack2(h0, h1); ph[1] = pack2(h2, h3);
    pl[0] = pack2(l0, l1); pl[1] = pack2(l2, l3);
}

// Row softmax over N=2048 -> P bf16 hi/lo
__global__ __launch_bounds__(256)
void softmax_k(const float* __restrict__ S,
               __nv_bfloat16* __restrict__ Ph, __nv_bfloat16* __restrict__ Pl)
{
    const int N = 2048;
    const float* p = S + (size_t)blockIdx.x * N;
    __nv_bfloat16* oh = Ph + (size_t)blockIdx.x * N;
    __nv_bfloat16* ol = Pl + (size_t)blockIdx.x * N;
    const int t = threadIdx.x;

    float v[8];
    float mx = -1e30f;
#pragma unroll
    for (int u = 0; u < 8; u++) {
        v[u] = p[t + 256 * u];
        mx = fmaxf(mx, v[u]);
    }
    __shared__ float red[8];
#pragma unroll
    for (int o = 16; o > 0; o >>= 1) mx = fmaxf(mx, __shfl_xor_sync(0xffffffffu, mx, o));
    if ((t & 31) == 0) red[t >> 5] = mx;
    __syncthreads();
    mx = red[0];
#pragma unroll
    for (int i = 1; i < 8; i++) mx = fmaxf(mx, red[i]);

    float s = 0.f;
#pragma unroll
    for (int u = 0; u < 8; u++) {
        v[u] = __expf(v[u] - mx);
        s += v[u];
    }
#pragma unroll
    for (int o = 16; o > 0; o >>= 1) s += __shfl_xor_sync(0xffffffffu, s, o);
    __syncthreads();
    if ((t & 31) == 0) red[t >> 5] = s;
    __syncthreads();
    s = red[0];
#pragma unroll
    for (int i = 1; i < 8; i++) s += red[i];

    const float inv = 1.f / s;
#pragma unroll
    for (int u = 0; u < 8; u++) {
        float pv = v[u] * inv;
        __nv_bfloat16 h, l;
        split_bf(pv, h, l);
        oh[t + 256 * u] = h;
        ol[t + 256 * u] = l;
    }
}

// LayerNorm over C=512 -> y bf16 hi/lo
__global__ __launch_bounds__(128)
void ln_k(const float* __restrict__ X, const float* __restrict__ g,
          const float* __restrict__ b,
          __nv_bfloat16* __restrict__ Yh, __nv_bfloat16* __restrict__ Yl)
{
    const int C = 512;
    const float* x = X + (size_t)blockIdx.x * C;
    const int t = threadIdx.x;

    float4 v = *reinterpret_cast<const float4*>(x + t * 4);
    float s = v.x + v.y + v.z + v.w;

    __shared__ float red[4];
#pragma unroll
    for (int o = 16; o > 0; o >>= 1) s += __shfl_xor_sync(0xffffffffu, s, o);
    if ((t & 31) == 0) red[t >> 5] = s;
    __syncthreads();
    const float mean = (red[0] + red[1] + red[2] + red[3]) * (1.f / 512.f);

    const float dx = v.x - mean, dy = v.y - mean, dz = v.z - mean, dw = v.w - mean;
    float q = dx * dx + dy * dy + dz * dz + dw * dw;
#pragma unroll
    for (int o = 16; o > 0; o >>= 1) q += __shfl_xor_sync(0xffffffffu, q, o);
    __syncthreads();
    if ((t & 31) == 0) red[t >> 5] = q;
    __syncthreads();
    const float var = (red[0] + red[1] + red[2] + red[3]) * (1.f / 512.f);
    const float rstd = rsqrtf(var + 1e-5f);

    float4 gg = *reinterpret_cast<const float4*>(g + t * 4);
    float4 bb = *reinterpret_cast<const float4*>(b + t * 4);
    float o0 = dx * rstd * gg.x + bb.x;
    float o1 = dy * rstd * gg.y + bb.y;
    float o2 = dz * rstd * gg.z + bb.z;
    float o3 = dw * rstd * gg.w + bb.w;

    __nv_bfloat16 h0, l0, h1, l1, h2, l2, h3, l3;
    split_bf(o0, h0, l0); split_bf(o1, h1, l1);
    split_bf(o2, h2, l2); split_bf(o3, h3, l3);
    const long base = (long)blockIdx.x * C + t * 4;
    unsigned* ph = reinterpret_cast<unsigned*>(Yh + base);
    unsigned* pl = reinterpret_cast<unsigned*>(Yl + base);
    ph[0] = pack2(h0, h1); ph[1] = pack2(h2, h3);
    pl[0] = pack2(l0, l1); pl[1] = pack2(l2, l3);
}

extern "C" void kernel_launch(void* const* d_in, const int* in_sizes, int n_in,
                              void* d_out, int out_size)
{
    const float* x_in  = (const float*)d_in[0];
    const float* qkv_w = (const float*)d_in[1];
    const float* qkv_b = (const float*)d_in[2];
    const float* ln_g  = (const float*)d_in[3];
    const float* ln_b  = (const float*)d_in[4];
    const float* fc1_w = (const float*)d_in[5];
    const float* fc1_b = (const float*)d_in[6];
    const float* fc2_w = (const float*)d_in[7];
    const float* fc2_b = (const float*)d_in[8];
    float* x = (float*)d_out;

    float* S;
    __nv_bfloat16 *xh, *xl, *qh, *ql, *kh, *kl, *vth, *vtl, *Ph, *Pl, *yh, *yl, *hh, *hl;
    __nv_bfloat16 *wqh, *wql, *w1h, *w1l, *w2h, *w2l;
    cudaGetSymbolAddress((void**)&S,   g_S);
    cudaGetSymbolAddress((void**)&xh,  g_xh);  cudaGetSymbolAddress((void**)&xl,  g_xl);
    cudaGetSymbolAddress((void**)&qh,  g_qh);  cudaGetSymbolAddress((void**)&ql,  g_ql);
    cudaGetSymbolAddress((void**)&kh,  g_kh);  cudaGetSymbolAddress((void**)&kl,  g_kl);
    cudaGetSymbolAddress((void**)&vth, g_vth); cudaGetSymbolAddress((void**)&vtl, g_vtl);
    cudaGetSymbolAddress((void**)&Ph,  g_Ph);  cudaGetSymbolAddress((void**)&Pl,  g_Pl);
    cudaGetSymbolAddress((void**)&yh,  g_yh);  cudaGetSymbolAddress((void**)&yl,  g_yl);
    cudaGetSymbolAddress((void**)&hh,  g_hh);  cudaGetSymbolAddress((void**)&hl,  g_hl);
    cudaGetSymbolAddress((void**)&wqh, g_wqh); cudaGetSymbolAddress((void**)&wql, g_wql);
    cudaGetSymbolAddress((void**)&w1h, g_w1h); cudaGetSymbolAddress((void**)&w1l, g_w1l);
    cudaGetSymbolAddress((void**)&w2h, g_w2h); cudaGetSymbolAddress((void**)&w2l, g_w2l);

    cudaFuncSetAttribute(gemm_bf16<0, true>,  cudaFuncAttributeMaxDynamicSharedMemorySize, GEMM_SMEM);
    cudaFuncSetAttribute(gemm_bf16<1, false>, cudaFuncAttributeMaxDynamicSharedMemorySize, GEMM_SMEM);
    cudaFuncSetAttribute(gemm_bf16<2, false>, cudaFuncAttributeMaxDynamicSharedMemorySize, GEMM_SMEM);
    cudaFuncSetAttribute(gemm_bf16<3, false>, cudaFuncAttributeMaxDynamicSharedMemorySize, GEMM_SMEM);
    cudaFuncSetAttribute(gemm_bf16<4, false>, cudaFuncAttributeMaxDynamicSharedMemorySize, GEMM_SMEM);

    const int Bn = 8, Nn = 2048, Cn = 512;
    const long xs = (long)Nn * Cn;
    const float scale = 0.044194173824159216f;  // 512^-0.5

    cudaMemcpyAsync(x, x_in, sizeof(float) * Bn * Nn * Cn, cudaMemcpyDeviceToDevice);

    // one-time pre-split of weights (transposed to [N][K]) and initial x
    wtrans_k<<<dim3(48, 16, 5), dim3(32, 8)>>>(qkv_w, wqh, wql, 512, 1536);
    wtrans_k<<<dim3(32, 16, 5), dim3(32, 8)>>>(fc1_w, w1h, w1l, 512, 1024);
    wtrans_k<<<dim3(16, 32, 5), dim3(32, 8)>>>(fc2_w, w2h, w2l, 1024, 512);
    xcvt_k<<<(int)((long)Bn * Nn * Cn / 4 / 256), 256>>>(x_in, xh, xl);

    for (int l = 0; l < 5; l++) {
        // qkv: A=x[2048x512], B=wqkvT[1536x512] -> q/k/vT bf16 (EPI=1)
        gemm_bf16<1, false><<<dim3(12, 16, 8), 256, GEMM_SMEM>>>(
            xh, xl, wqh + (long)l * 1536 * 512, wql + (long)l * 1536 * 512,
            qkv_b + l * 3 * Cn, nullptr, nullptr,
            Nn, 1536, 512, 512, 512, 0, xs, 0, 0, 1.f);

        // S = scale*q@k^T + mask (EPI=4)
        gemm_bf16<4, false><<<dim3(16, 16, 8), 256, GEMM_SMEM>>>(
            qh, ql, kh, kl, nullptr, nullptr, S,
            Nn, Nn, 512, 512, 512, Nn, xs, xs, (long)Nn * Nn, scale);

        // P = softmax(S) -> bf16 hi/lo
        softmax_k<<<Bn * Nn, 256>>>(S, Ph, Pl);

        // x = P @ v (A=P[2048x2048], B=vT[512x2048], K-trunc, EPI=0)
        gemm_bf16<0, true><<<dim3(4, 16, 8), 256, GEMM_SMEM>>>(
            Ph, Pl, vth, vtl, nullptr, nullptr, x,
            Nn, Cn, Nn, Nn, Nn, Cn, (long)Nn * Nn, (long)Cn * Nn, xs, 1.f);

        // y = layernorm(x) -> bf16 hi/lo
        ln_k<<<Bn * Nn, 128>>>(x, ln_g + l * Cn, ln_b + l * Cn, yh, yl);

        // h = gelu(y @ fc1 + b) -> bf16 hi/lo (EPI=2)
        gemm_bf16<2, false><<<dim3(8, 16, 8), 256, GEMM_SMEM>>>(
            yh, yl, w1h + (long)l * 1024 * 512, w1l + (long)l * 1024 * 512,
            fc1_b + l * 2 * Cn, nullptr, nullptr,
            Nn, 1024, 512, 512, 512, 1024, xs, 0, (long)Nn * 1024, 1.f);

        // x = x + h @ fc2 + b -> fp32 x + bf16 hi/lo x (EPI=3)
        gemm_bf16<3, false><<<dim3(4, 16, 8), 256, GEMM_SMEM>>>(
            hh, hl, w2h + (long)l * 512 * 1024, w2l + (long)l * 512 * 1024,
            fc2_b + l * Cn, x, x,
            Nn, Cn, 1024, 1024, 1024, Cn, (long)Nn * 1024, 0, xs, 1.f);
    }
}

// round 15
// speedup vs baseline: 2.8920x; 1.0961x over previous
#include <cuda_runtime.h>
#include <cuda_bf16.h>
#include <math.h>

// ---------------------------------------------------------------------------
// maskedContextModel: B=8, N=2048, C=512, L=5
// Round 13: pre-split bf16 hi/lo planes + ldmatrix.x4 fragment feed.
// 3-term bf16 MMA (ah*bh + ah*bl + al*bh, fp32 accum), cp.async BK=32
// double buffer, 2 CTA/SM. Mask block-skip + K-truncation retained.
// ---------------------------------------------------------------------------

#define NB  8
#define NN_ 2048
#define CC  512

__device__ float g_S[(size_t)NB * NN_ * NN_];

__device__ __nv_bfloat16 g_xh[(size_t)NB * NN_ * CC],  g_xl[(size_t)NB * NN_ * CC];
__device__ __nv_bfloat16 g_qh[(size_t)NB * NN_ * CC],  g_ql[(size_t)NB * NN_ * CC];
__device__ __nv_bfloat16 g_kh[(size_t)NB * NN_ * CC],  g_kl[(size_t)NB * NN_ * CC];
__device__ __nv_bfloat16 g_vth[(size_t)NB * CC * NN_], g_vtl[(size_t)NB * CC * NN_];
__device__ __nv_bfloat16 g_Ph[(size_t)NB * NN_ * NN_], g_Pl[(size_t)NB * NN_ * NN_];
__device__ __nv_bfloat16 g_yh[(size_t)NB * NN_ * CC],  g_yl[(size_t)NB * NN_ * CC];
__device__ __nv_bfloat16 g_hh[(size_t)NB * NN_ * 1024], g_hl[(size_t)NB * NN_ * 1024];

__device__ __nv_bfloat16 g_wqh[(size_t)5 * 1536 * 512], g_wql[(size_t)5 * 1536 * 512];
__device__ __nv_bfloat16 g_w1h[(size_t)5 * 1024 * 512], g_w1l[(size_t)5 * 1024 * 512];
__device__ __nv_bfloat16 g_w2h[(size_t)5 * 512 * 1024], g_w2l[(size_t)5 * 512 * 1024];

__device__ __forceinline__ void split_bf(float v, __nv_bfloat16& h, __nv_bfloat16& l) {
    h = __float2bfloat16_rn(v);
    l = __float2bfloat16_rn(v - __bfloat162float(h));
}
__device__ __forceinline__ unsigned pack2(__nv_bfloat16 a, __nv_bfloat16 b) {
    unsigned ua = *reinterpret_cast<unsigned short*>(&a);
    unsigned ub = *reinterpret_cast<unsigned short*>(&b);
    return ua | (ub << 16);
}

__device__ __forceinline__ void mma_bf16(float& c0, float& c1, float& c2, float& c3,
                                         unsigned a0, unsigned a1, unsigned a2, unsigned a3,
                                         unsigned b0, unsigned b1) {
    asm volatile(
        "mma.sync.aligned.m16n8k16.row.col.f32.bf16.bf16.f32 "
        "{%0,%1,%2,%3}, {%4,%5,%6,%7}, {%8,%9}, {%0,%1,%2,%3};"
        : "+f"(c0), "+f"(c1), "+f"(c2), "+f"(c3)
        : "r"(a0), "r"(a1), "r"(a2), "r"(a3), "r"(b0), "r"(b1));
}

__device__ __forceinline__ void ldsm4(unsigned& r0, unsigned& r1, unsigned& r2, unsigned& r3,
                                      unsigned addr) {
    asm volatile("ldmatrix.sync.aligned.m8n8.x4.shared.b16 {%0,%1,%2,%3}, [%4];"
                 : "=r"(r0), "=r"(r1), "=r"(r2), "=r"(r3) : "r"(addr));
}

__device__ __forceinline__ void cp16(unsigned* s, const __nv_bfloat16* g) {
    unsigned sa = (unsigned)__cvta_generic_to_shared(s);
    asm volatile("cp.async.cg.shared.global [%0], [%1], 16;" :: "r"(sa), "l"(g));
}
__device__ __forceinline__ void cp_commit() { asm volatile("cp.async.commit_group;"); }
__device__ __forceinline__ void cp_wait0()  { asm volatile("cp.async.wait_group 0;" ::: "memory"); }

#define PW    20            // words per tile row = 40 halves (32 used + 8 pad)
#define TILEW (128 * PW)    // 2560 words per plane-buffer
static const int GEMM_SMEM = 8 * TILEW * 4;   // 81920 B

// EPI: 0 = PV (fp32 out), 1 = QKV (bias + split q/k/vT), 2 = fc1 (gelu -> h),
//      3 = fc2 (bias+resid -> fp32 x + split x), 4 = S (alpha + mask)
template <int EPI, bool MASKK>
__global__ __launch_bounds__(256, 2)
void gemm_bf16(const __nv_bfloat16* __restrict__ Ah, const __nv_bfloat16* __restrict__ Al,
               const __nv_bfloat16* __restrict__ Bh, const __nv_bfloat16* __restrict__ Bl,
               const float* __restrict__ bias, const float* __restrict__ resid,
               float* outF,
               int M, int N, int K, int lda, int ldb, int ldc,
               long sA, long sB, long sC, float alpha)
{
    extern __shared__ unsigned sm[];

    const int bz   = blockIdx.z;
    const int tid  = threadIdx.x;
    const int brow = blockIdx.y, bcol = blockIdx.x;

    const int lane  = tid & 31;
    const int warp  = tid >> 5;
    const int warpM = warp & 1;
    const int warpN = warp >> 1;
    const int kA    = lane & 3;
    const int grp   = lane >> 2;
    const int mBase = warpM * 64;
    const int nBase = warpN * 32;

    if (EPI == 0 || EPI == 3 || EPI == 4) outF += (long)bz * sC;

    if (EPI == 4) {
        if ((bcol >= 8 || brow >= 8) && bcol > brow) {
            float2 mk = make_float2(-1000.f, -1000.f);
#pragma unroll
            for (int mt = 0; mt < 4; mt++) {
                const long gr0 = brow * 128 + mBase + mt * 16 + grp;
#pragma unroll
                for (int nt = 0; nt < 4; nt++) {
                    const int gc = bcol * 128 + nBase + nt * 8 + kA * 2;
                    *reinterpret_cast<float2*>(&outF[gr0 * ldc + gc]) = mk;
                    *reinterpret_cast<float2*>(&outF[(gr0 + 8) * ldc + gc]) = mk;
                }
            }
            return;
        }
    }

    Ah += (long)bz * sA;  Al += (long)bz * sA;
    Bh += (long)bz * sB;  Bl += (long)bz * sB;

    int Keff = K;
    if (MASKK) Keff = (brow < 8) ? 1024 : (brow + 1) * 128;

    // ---- gmem loader coords ----
    const int row = tid >> 1;
    const int hf  = tid & 1;
    const __nv_bfloat16* agH = Ah + (long)(brow * 128 + row) * lda + hf * 16;
    const __nv_bfloat16* agL = Al + (long)(brow * 128 + row) * lda + hf * 16;
    const __nv_bfloat16* bgH = Bh + (long)(bcol * 128 + row) * ldb + hf * 16;
    const __nv_bfloat16* bgL = Bl + (long)(bcol * 128 + row) * ldb + hf * 16;
    const int dstw = row * PW + hf * 8;

    // ---- ldmatrix per-lane address pieces (half-index based) ----
    const int t4 = lane >> 3;        // tile id 0..3
    const int r8 = lane & 7;         // row within tile
    // A x4 tiles: t0=(m0-7,k0-7) t1=(m8-15,k0-7) t2=(m0-7,k8-15) t3=(m8-15,k8-15)
    const int aHalfBase = (mBase + (t4 & 1) * 8 + r8) * 40 + (t4 >> 1) * 8;
    // B x4 tiles: t0=(nA,k0-7) t1=(nA,k8-15) t2=(nB,k0-7) t3=(nB,k8-15)
    const int bHalfBase = (nBase + (t4 >> 1) * 8 + r8) * 40 + (t4 & 1) * 8;

    const unsigned smBase = (unsigned)__cvta_generic_to_shared(sm);

    float c[4][4][4];
#pragma unroll
    for (int mt = 0; mt < 4; mt++)
#pragma unroll
        for (int nt = 0; nt < 4; nt++)
#pragma unroll
            for (int i = 0; i < 4; i++) c[mt][nt][i] = 0.f;

    // ---- preload stage 0 ----
    {
        cp16(sm + 0 * TILEW + dstw, agH);      cp16(sm + 0 * TILEW + dstw + 4, agH + 8);
        cp16(sm + 2 * TILEW + dstw, agL);      cp16(sm + 2 * TILEW + dstw + 4, agL + 8);
        cp16(sm + 4 * TILEW + dstw, bgH);      cp16(sm + 4 * TILEW + dstw + 4, bgH + 8);
        cp16(sm + 6 * TILEW + dstw, bgL);      cp16(sm + 6 * TILEW + dstw + 4, bgL + 8);
        cp_commit();
        cp_wait0();
    }
    __syncthreads();

    const int nstages = Keff >> 5;      // BK = 32
    int buf = 0;
    for (int t = 0; t < nstages; ++t) {
        const bool more = (t + 1) < nstages;
        if (more) {
            const int k0 = (t + 1) * 32;
            const int nb = buf ^ 1;
            cp16(sm + nb * TILEW + dstw, agH + k0);
            cp16(sm + nb * TILEW + dstw + 4, agH + k0 + 8);
            cp16(sm + (2 + nb) * TILEW + dstw, agL + k0);
            cp16(sm + (2 + nb) * TILEW + dstw + 4, agL + k0 + 8);
            cp16(sm + (4 + nb) * TILEW + dstw, bgH + k0);
            cp16(sm + (4 + nb) * TILEW + dstw + 4, bgH + k0 + 8);
            cp16(sm + (6 + nb) * TILEW + dstw, bgL + k0);
            cp16(sm + (6 + nb) * TILEW + dstw + 4, bgL + k0 + 8);
            cp_commit();
        }

        const unsigned aH0 = smBase + (buf * TILEW) * 4       + aHalfBase * 2;
        const unsigned aL0 = smBase + ((2 + buf) * TILEW) * 4 + aHalfBase * 2;
        const unsigned bH0 = smBase + ((4 + buf) * TILEW) * 4 + bHalfBase * 2;
        const unsigned bL0 = smBase + ((6 + buf) * TILEW) * 4 + bHalfBase * 2;

#pragma unroll
        for (int ks = 0; ks < 2; ks++) {
            const int ko = ks * 32;              // ks*16 halves -> bytes

            unsigned ah[4][4];
#pragma unroll
            for (int mt = 0; mt < 4; mt++)
                ldsm4(ah[mt][0], ah[mt][1], ah[mt][2], ah[mt][3],
                      aH0 + mt * (16 * 40 * 2) + ko);

            unsigned bh[4][2];
#pragma unroll
            for (int np = 0; np < 2; np++)
                ldsm4(bh[2 * np][0], bh[2 * np][1], bh[2 * np + 1][0], bh[2 * np + 1][1],
                      bH0 + np * (16 * 40 * 2) + ko);

#pragma unroll
            for (int mt = 0; mt < 4; mt++)
#pragma unroll
                for (int nt = 0; nt < 4; nt++)
                    mma_bf16(c[mt][nt][0], c[mt][nt][1], c[mt][nt][2], c[mt][nt][3],
                             ah[mt][0], ah[mt][1], ah[mt][2], ah[mt][3],
                             bh[nt][0], bh[nt][1]);

            unsigned bl[4][2];
#pragma unroll
            for (int np = 0; np < 2; np++)
                ldsm4(bl[2 * np][0], bl[2 * np][1], bl[2 * np + 1][0], bl[2 * np + 1][1],
                      bL0 + np * (16 * 40 * 2) + ko);

#pragma unroll
            for (int mt = 0; mt < 4; mt++)
#pragma unroll
                for (int nt = 0; nt < 4; nt++)
                    mma_bf16(c[mt][nt][0], c[mt][nt][1], c[mt][nt][2], c[mt][nt][3],
                             ah[mt][0], ah[mt][1], ah[mt][2], ah[mt][3],
                             bl[nt][0], bl[nt][1]);

            unsigned al[4][4];
#pragma unroll
            for (int mt = 0; mt < 4; mt++)
                ldsm4(al[mt][0], al[mt][1], al[mt][2], al[mt][3],
                      aL0 + mt * (16 * 40 * 2) + ko);

#pragma unroll
            for (int mt = 0; mt < 4; mt++)
#pragma unroll
                for (int nt = 0; nt < 4; nt++)
                    mma_bf16(c[mt][nt][0], c[mt][nt][1], c[mt][nt][2], c[mt][nt][3],
                             al[mt][0], al[mt][1], al[mt][2], al[mt][3],
                             bh[nt][0], bh[nt][1]);
        }

        if (more) {
            cp_wait0();
            __syncthreads();
            buf ^= 1;
        }
    }

    // ---- epilogue ----
#pragma unroll
    for (int mt = 0; mt < 4; mt++) {
        const int gr0 = brow * 128 + mBase + mt * 16 + grp;
#pragma unroll
        for (int nt = 0; nt < 4; nt++) {
            const int gc = bcol * 128 + nBase + nt * 8 + kA * 2;
#pragma unroll
            for (int h = 0; h < 2; h++) {
                const int gr = gr0 + h * 8;
                float v0 = c[mt][nt][h * 2 + 0];
                float v1 = c[mt][nt][h * 2 + 1];

                if (EPI == 0) {
                    *reinterpret_cast<float2*>(&outF[(long)gr * ldc + gc]) = make_float2(v0, v1);
                } else if (EPI == 4) {
                    const int half = N >> 1;
                    const bool ok0 = (gr < half) ? (gc < half) : (gc <= gr);
                    const bool ok1 = (gr < half) ? (gc + 1 < half) : (gc + 1 <= gr);
                    v0 = alpha * v0 + (ok0 ? 0.f : -1000.f);
                    v1 = alpha * v1 + (ok1 ? 0.f : -1000.f);
                    *reinterpret_cast<float2*>(&outF[(long)gr * ldc + gc]) = make_float2(v0, v1);
                } else if (EPI == 1) {
                    v0 += bias[gc];
                    v1 += bias[gc + 1];
                    __nv_bfloat16 h0, l0, h1, l1;
                    split_bf(v0, h0, l0);
                    split_bf(v1, h1, l1);
                    const int seg = gc >> 9;
                    const int col = gc & 511;
                    if (seg == 0) {
                        const long idx = ((long)bz * NN_ + gr) * CC + col;
                        *reinterpret_cast<unsigned*>(&g_qh[idx]) = pack2(h0, h1);
                        *reinterpret_cast<unsigned*>(&g_ql[idx]) = pack2(l0, l1);
                    } else if (seg == 1) {
                        const long idx = ((long)bz * NN_ + gr) * CC + col;
                        *reinterpret_cast<unsigned*>(&g_kh[idx]) = pack2(h0, h1);
                        *reinterpret_cast<unsigned*>(&g_kl[idx]) = pack2(l0, l1);
                    } else {
                        const long i0 = ((long)bz * CC + col) * NN_ + gr;
                        const long i1 = ((long)bz * CC + col + 1) * NN_ + gr;
                        g_vth[i0] = h0; g_vtl[i0] = l0;
                        g_vth[i1] = h1; g_vtl[i1] = l1;
                    }
                } else if (EPI == 2) {
                    v0 += bias[gc];
                    v1 += bias[gc + 1];
                    v0 = 0.5f * v0 * (1.f + erff(v0 * 0.70710678118654752f));
                    v1 = 0.5f * v1 * (1.f + erff(v1 * 0.70710678118654752f));
                    __nv_bfloat16 h0, l0, h1, l1;
                    split_bf(v0, h0, l0);
                    split_bf(v1, h1, l1);
                    const long idx = (long)bz * sC + (long)gr * ldc + gc;
                    *reinterpret_cast<unsigned*>(&g_hh[idx]) = pack2(h0, h1);
                    *reinterpret_cast<unsigned*>(&g_hl[idx]) = pack2(l0, l1);
                } else {  // EPI == 3
                    const float* rr = resid + (long)bz * sC + (long)gr * ldc + gc;
                    v0 += bias[gc] + rr[0];
                    v1 += bias[gc + 1] + rr[1];
                    *reinterpret_cast<float2*>(&outF[(long)gr * ldc + gc]) = make_float2(v0, v1);
                    __nv_bfloat16 h0, l0, h1, l1;
                    split_bf(v0, h0, l0);
                    split_bf(v1, h1, l1);
                    const long idx = (long)bz * sC + (long)gr * ldc + gc;
                    *reinterpret_cast<unsigned*>(&g_xh[idx]) = pack2(h0, h1);
                    *reinterpret_cast<unsigned*>(&g_xl[idx]) = pack2(l0, l1);
                }
            }
        }
    }
}

// Weight transpose + bf16 hi/lo split: W [L][K][N] fp32 -> T [L][N][K] bf16 x2
__global__ void wtrans_k(const float* __restrict__ W,
                         __nv_bfloat16* __restrict__ Th, __nv_bfloat16* __restrict__ Tl,
                         int K, int N)
{
    __shared__ float t[32][33];
    const int n0 = blockIdx.x * 32, k0 = blockIdx.y * 32, l = blockIdx.z;
    const int tx = threadIdx.x, ty = threadIdx.y;
    const float* Wl = W + (long)l * K * N;
#pragma unroll
    for (int i = 0; i < 4; i++)
        t[ty + 8 * i][tx] = Wl[(long)(k0 + ty + 8 * i) * N + n0 + tx];
    __syncthreads();
    const long ob = (long)l * N * K;
#pragma unroll
    for (int i = 0; i < 4; i++) {
        const int n = n0 + ty + 8 * i;
        float v = t[tx][ty + 8 * i];
        __nv_bfloat16 h, lo;
        split_bf(v, h, lo);
        Th[ob + (long)n * K + k0 + tx] = h;
        Tl[ob + (long)n * K + k0 + tx] = lo;
    }
}

// Initial x -> bf16 hi/lo planes
__global__ void xcvt_k(const float* __restrict__ x,
                       __nv_bfloat16* __restrict__ Xh, __nv_bfloat16* __restrict__ Xl)
{
    const long i = (long)blockIdx.x * 256 + threadIdx.x;
    float4 v = reinterpret_cast<const float4*>(x)[i];
    __nv_bfloat16 h0, l0, h1, l1, h2, l2, h3, l3;
    split_bf(v.x, h0, l0); split_bf(v.y, h1, l1);
    split_bf(v.z, h2, l2); split_bf(v.w, h3, l3);
    unsigned* ph = reinterpret_cast<unsigned*>(Xh) + i * 2;
    unsigned* pl = reinterpret_cast<unsigned*>(Xl) + i * 2;
    ph[0] = pack2(h0, h1); ph[1] = pack2(h2, h3);
    pl[0] = pack2(l0, l1); pl[1] = pack2(l2, l3);
}

// Row softmax over N=2048 -> P bf16 hi/lo
__global__ __launch_bounds__(256)
void softmax_k(const float* __restrict__ S,
               __nv_bfloat16* __restrict__ Ph, __nv_bfloat16* __restrict__ Pl)
{
    const int N = 2048;
    const float* p = S + (size_t)blockIdx.x * N;
    __nv_bfloat16* oh = Ph + (size_t)blockIdx.x * N;
    __nv_bfloat16* ol = Pl + (size_t)blockIdx.x * N;
    const int t = threadIdx.x;

    float v[8];
    float mx = -1e30f;
#pragma unroll
    for (int u = 0; u < 8; u++) {
        v[u] = p[t + 256 * u];
        mx = fmaxf(mx, v[u]);
    }
    __shared__ float red[8];
#pragma unroll
    for (int o = 16; o > 0; o >>= 1) mx = fmaxf(mx, __shfl_xor_sync(0xffffffffu, mx, o));
    if ((t & 31) == 0) red[t >> 5] = mx;
    __syncthreads();
    mx = red[0];
#pragma unroll
    for (int i = 1; i < 8; i++) mx = fmaxf(mx, red[i]);

    float s = 0.f;
#pragma unroll
    for (int u = 0; u < 8; u++) {
        v[u] = __expf(v[u] - mx);
        s += v[u];
    }
#pragma unroll
    for (int o = 16; o > 0; o >>= 1) s += __shfl_xor_sync(0xffffffffu, s, o);
    __syncthreads();
    if ((t & 31) == 0) red[t >> 5] = s;
    __syncthreads();
    s = red[0];
#pragma unroll
    for (int i = 1; i < 8; i++) s += red[i];

    const float inv = 1.f / s;
#pragma unroll
    for (int u = 0; u < 8; u++) {
        float pv = v[u] * inv;
        __nv_bfloat16 h, l;
        split_bf(pv, h, l);
        oh[t + 256 * u] = h;
        ol[t + 256 * u] = l;
    }
}

// LayerNorm over C=512 -> y bf16 hi/lo
__global__ __launch_bounds__(128)
void ln_k(const float* __restrict__ X, const float* __restrict__ g,
          const float* __restrict__ b,
          __nv_bfloat16* __restrict__ Yh, __nv_bfloat16* __restrict__ Yl)
{
    const int C = 512;
    const float* x = X + (size_t)blockIdx.x * C;
    const int t = threadIdx.x;

    float4 v = *reinterpret_cast<const float4*>(x + t * 4);
    float s = v.x + v.y + v.z + v.w;

    __shared__ float red[4];
#pragma unroll
    for (int o = 16; o > 0; o >>= 1) s += __shfl_xor_sync(0xffffffffu, s, o);
    if ((t & 31) == 0) red[t >> 5] = s;
    __syncthreads();
    const float mean = (red[0] + red[1] + red[2] + red[3]) * (1.f / 512.f);

    const float dx = v.x - mean, dy = v.y - mean, dz = v.z - mean, dw = v.w - mean;
    float q = dx * dx + dy * dy + dz * dz + dw * dw;
#pragma unroll
    for (int o = 16; o > 0; o >>= 1) q += __shfl_xor_sync(0xffffffffu, q, o);
    __syncthreads();
    if ((t & 31) == 0) red[t >> 5] = q;
    __syncthreads();
    const float var = (red[0] + red[1] + red[2] + red[3]) * (1.f / 512.f);
    const float rstd = rsqrtf(var + 1e-5f);

    float4 gg = *reinterpret_cast<const float4*>(g + t * 4);
    float4 bb = *reinterpret_cast<const float4*>(b + t * 4);
    float o0 = dx * rstd * gg.x + bb.x;
    float o1 = dy * rstd * gg.y + bb.y;
    float o2 = dz * rstd * gg.z + bb.z;
    float o3 = dw * rstd * gg.w + bb.w;

    __nv_bfloat16 h0, l0, h1, l1, h2, l2, h3, l3;
    split_bf(o0, h0, l0); split_bf(o1, h1, l1);
    split_bf(o2, h2, l2); split_bf(o3, h3, l3);
    const long base = (long)blockIdx.x * C + t * 4;
    unsigned* ph = reinterpret_cast<unsigned*>(Yh + base);
    unsigned* pl = reinterpret_cast<unsigned*>(Yl + base);
    ph[0] = pack2(h0, h1); ph[1] = pack2(h2, h3);
    pl[0] = pack2(l0, l1); pl[1] = pack2(l2, l3);
}

extern "C" void kernel_launch(void* const* d_in, const int* in_sizes, int n_in,
                              void* d_out, int out_size)
{
    const float* x_in  = (const float*)d_in[0];
    const float* qkv_w = (const float*)d_in[1];
    const float* qkv_b = (const float*)d_in[2];
    const float* ln_g  = (const float*)d_in[3];
    const float* ln_b  = (const float*)d_in[4];
    const float* fc1_w = (const float*)d_in[5];
    const float* fc1_b = (const float*)d_in[6];
    const float* fc2_w = (const float*)d_in[7];
    const float* fc2_b = (const float*)d_in[8];
    float* x = (float*)d_out;

    float* S;
    __nv_bfloat16 *xh, *xl, *qh, *ql, *kh, *kl, *vth, *vtl, *Ph, *Pl, *yh, *yl, *hh, *hl;
    __nv_bfloat16 *wqh, *wql, *w1h, *w1l, *w2h, *w2l;
    cudaGetSymbolAddress((void**)&S,   g_S);
    cudaGetSymbolAddress((void**)&xh,  g_xh);  cudaGetSymbolAddress((void**)&xl,  g_xl);
    cudaGetSymbolAddress((void**)&qh,  g_qh);  cudaGetSymbolAddress((void**)&ql,  g_ql);
    cudaGetSymbolAddress((void**)&kh,  g_kh);  cudaGetSymbolAddress((void**)&kl,  g_kl);
    cudaGetSymbolAddress((void**)&vth, g_vth); cudaGetSymbolAddress((void**)&vtl, g_vtl);
    cudaGetSymbolAddress((void**)&Ph,  g_Ph);  cudaGetSymbolAddress((void**)&Pl,  g_Pl);
    cudaGetSymbolAddress((void**)&yh,  g_yh);  cudaGetSymbolAddress((void**)&yl,  g_yl);
    cudaGetSymbolAddress((void**)&hh,  g_hh);  cudaGetSymbolAddress((void**)&hl,  g_hl);
    cudaGetSymbolAddress((void**)&wqh, g_wqh); cudaGetSymbolAddress((void**)&wql, g_wql);
    cudaGetSymbolAddress((void**)&w1h, g_w1h); cudaGetSymbolAddress((void**)&w1l, g_w1l);
    cudaGetSymbolAddress((void**)&w2h, g_w2h); cudaGetSymbolAddress((void**)&w2l, g_w2l);

    cudaFuncSetAttribute(gemm_bf16<0, true>,  cudaFuncAttributeMaxDynamicSharedMemorySize, GEMM_SMEM);
    cudaFuncSetAttribute(gemm_bf16<1, false>, cudaFuncAttributeMaxDynamicSharedMemorySize, GEMM_SMEM);
    cudaFuncSetAttribute(gemm_bf16<2, false>, cudaFuncAttributeMaxDynamicSharedMemorySize, GEMM_SMEM);
    cudaFuncSetAttribute(gemm_bf16<3, false>, cudaFuncAttributeMaxDynamicSharedMemorySize, GEMM_SMEM);
    cudaFuncSetAttribute(gemm_bf16<4, false>, cudaFuncAttributeMaxDynamicSharedMemorySize, GEMM_SMEM);

    const int Bn = 8, Nn = 2048, Cn = 512;
    const long xs = (long)Nn * Cn;
    const float scale = 0.044194173824159216f;  // 512^-0.5

    cudaMemcpyAsync(x, x_in, sizeof(float) * Bn * Nn * Cn, cudaMemcpyDeviceToDevice);

    // one-time pre-split of weights (transposed to [N][K]) and initial x
    wtrans_k<<<dim3(48, 16, 5), dim3(32, 8)>>>(qkv_w, wqh, wql, 512, 1536);
    wtrans_k<<<dim3(32, 16, 5), dim3(32, 8)>>>(fc1_w, w1h, w1l, 512, 1024);
    wtrans_k<<<dim3(16, 32, 5), dim3(32, 8)>>>(fc2_w, w2h, w2l, 1024, 512);
    xcvt_k<<<(int)((long)Bn * Nn * Cn / 4 / 256), 256>>>(x_in, xh, xl);

    for (int l = 0; l < 5; l++) {
        // qkv (EPI=1)
        gemm_bf16<1, false><<<dim3(12, 16, 8), 256, GEMM_SMEM>>>(
            xh, xl, wqh + (long)l * 1536 * 512, wql + (long)l * 1536 * 512,
            qkv_b + l * 3 * Cn, nullptr, nullptr,
            Nn, 1536, 512, 512, 512, 0, xs, 0, 0, 1.f);

        // S = scale*q@k^T + mask (EPI=4)
        gemm_bf16<4, false><<<dim3(16, 16, 8), 256, GEMM_SMEM>>>(
            qh, ql, kh, kl, nullptr, nullptr, S,
            Nn, Nn, 512, 512, 512, Nn, xs, xs, (long)Nn * Nn, scale);

        // P = softmax(S)
        softmax_k<<<Bn * Nn, 256>>>(S, Ph, Pl);

        // x = P @ v (EPI=0, K-trunc)
        gemm_bf16<0, true><<<dim3(4, 16, 8), 256, GEMM_SMEM>>>(
            Ph, Pl, vth, vtl, nullptr, nullptr, x,
            Nn, Cn, Nn, Nn, Nn, Cn, (long)Nn * Nn, (long)Cn * Nn, xs, 1.f);

        // y = layernorm(x)
        ln_k<<<Bn * Nn, 128>>>(x, ln_g + l * Cn, ln_b + l * Cn, yh, yl);

        // h = gelu(y @ fc1 + b) (EPI=2)
        gemm_bf16<2, false><<<dim3(8, 16, 8), 256, GEMM_SMEM>>>(
            yh, yl, w1h + (long)l * 1024 * 512, w1l + (long)l * 1024 * 512,
            fc1_b + l * 2 * Cn, nullptr, nullptr,
            Nn, 1024, 512, 512, 512, 1024, xs, 0, (long)Nn * 1024, 1.f);

        // x = x + h @ fc2 + b (EPI=3)
        gemm_bf16<3, false><<<dim3(4, 16, 8), 256, GEMM_SMEM>>>(
            hh, hl, w2h + (long)l * 512 * 1024, w2l + (long)l * 512 * 1024,
            fc2_b + l * Cn, x, x,
            Nn, Cn, 1024, 1024, 1024, Cn, (long)Nn * 1024, 0, xs, 1.f);
    }
}

// round 17
// speedup vs baseline: 2.9273x; 1.0122x over previous
#include <cuda_runtime.h>
#include <cuda_bf16.h>
#include <math.h>

// ---------------------------------------------------------------------------
// maskedContextModel: B=8, N=2048, C=512, L=5
// Round 16: R13 base (pre-split bf16 hi/lo planes + ldmatrix.x4 feed,
// 3-term bf16 MMA, cp.async BK=32 double buffer, 2 CTA/SM) +
// mask-aware vectorized softmax, full masked-S-tile skip, ldsm reorder.
// (tcgen05 unavailable: harness targets sm_103 family, not sm_103a.)
// ---------------------------------------------------------------------------

#define NB  8
#define NN_ 2048
#define CC  512

__device__ float g_S[(size_t)NB * NN_ * NN_];

__device__ __nv_bfloat16 g_xh[(size_t)NB * NN_ * CC],  g_xl[(size_t)NB * NN_ * CC];
__device__ __nv_bfloat16 g_qh[(size_t)NB * NN_ * CC],  g_ql[(size_t)NB * NN_ * CC];
__device__ __nv_bfloat16 g_kh[(size_t)NB * NN_ * CC],  g_kl[(size_t)NB * NN_ * CC];
__device__ __nv_bfloat16 g_vth[(size_t)NB * CC * NN_], g_vtl[(size_t)NB * CC * NN_];
__device__ __nv_bfloat16 g_Ph[(size_t)NB * NN_ * NN_], g_Pl[(size_t)NB * NN_ * NN_];
__device__ __nv_bfloat16 g_yh[(size_t)NB * NN_ * CC],  g_yl[(size_t)NB * NN_ * CC];
__device__ __nv_bfloat16 g_hh[(size_t)NB * NN_ * 1024], g_hl[(size_t)NB * NN_ * 1024];

__device__ __nv_bfloat16 g_wqh[(size_t)5 * 1536 * 512], g_wql[(size_t)5 * 1536 * 512];
__device__ __nv_bfloat16 g_w1h[(size_t)5 * 1024 * 512], g_w1l[(size_t)5 * 1024 * 512];
__device__ __nv_bfloat16 g_w2h[(size_t)5 * 512 * 1024], g_w2l[(size_t)5 * 512 * 1024];

__device__ __forceinline__ void split_bf(float v, __nv_bfloat16& h, __nv_bfloat16& l) {
    h = __float2bfloat16_rn(v);
    l = __float2bfloat16_rn(v - __bfloat162float(h));
}
__device__ __forceinline__ unsigned pack2(__nv_bfloat16 a, __nv_bfloat16 b) {
    unsigned ua = *reinterpret_cast<unsigned short*>(&a);
    unsigned ub = *reinterpret_cast<unsigned short*>(&b);
    return ua | (ub << 16);
}

__device__ __forceinline__ void mma_bf16(float& c0, float& c1, float& c2, float& c3,
                                         unsigned a0, unsigned a1, unsigned a2, unsigned a3,
                                         unsigned b0, unsigned b1) {
    asm volatile(
        "mma.sync.aligned.m16n8k16.row.col.f32.bf16.bf16.f32 "
        "{%0,%1,%2,%3}, {%4,%5,%6,%7}, {%8,%9}, {%0,%1,%2,%3};"
        : "+f"(c0), "+f"(c1), "+f"(c2), "+f"(c3)
        : "r"(a0), "r"(a1), "r"(a2), "r"(a3), "r"(b0), "r"(b1));
}

__device__ __forceinline__ void ldsm4(unsigned& r0, unsigned& r1, unsigned& r2, unsigned& r3,
                                      unsigned addr) {
    asm volatile("ldmatrix.sync.aligned.m8n8.x4.shared.b16 {%0,%1,%2,%3}, [%4];"
                 : "=r"(r0), "=r"(r1), "=r"(r2), "=r"(r3) : "r"(addr));
}

__device__ __forceinline__ void cp16(unsigned* s, const __nv_bfloat16* g) {
    unsigned sa = (unsigned)__cvta_generic_to_shared(s);
    asm volatile("cp.async.cg.shared.global [%0], [%1], 16;" :: "r"(sa), "l"(g));
}
__device__ __forceinline__ void cp_commit() { asm volatile("cp.async.commit_group;"); }
__device__ __forceinline__ void cp_wait0()  { asm volatile("cp.async.wait_group 0;" ::: "memory"); }

#define PW    20            // words per tile row = 40 halves (32 used + 8 pad)
#define TILEW (128 * PW)    // 2560 words per plane-buffer
static const int GEMM_SMEM = 8 * TILEW * 4;   // 81920 B

// EPI: 0 = PV (fp32 out), 1 = QKV (bias + split q/k/vT), 2 = fc1 (gelu -> h),
//      3 = fc2 (bias+resid -> fp32 x + split x), 4 = S (alpha + mask)
template <int EPI, bool MASKK>
__global__ __launch_bounds__(256, 2)
void gemm_bf16(const __nv_bfloat16* __restrict__ Ah, const __nv_bfloat16* __restrict__ Al,
               const __nv_bfloat16* __restrict__ Bh, const __nv_bfloat16* __restrict__ Bl,
               const float* __restrict__ bias, const float* __restrict__ resid,
               float* outF,
               int M, int N, int K, int lda, int ldb, int ldc,
               long sA, long sB, long sC, float alpha)
{
    extern __shared__ unsigned sm[];

    const int bz   = blockIdx.z;
    const int tid  = threadIdx.x;
    const int brow = blockIdx.y, bcol = blockIdx.x;

    // fully masked S tile: softmax is mask-aware and never reads it -> no work
    if (EPI == 4 && ((bcol >= 8 || brow >= 8) && bcol > brow)) return;

    const int lane  = tid & 31;
    const int warp  = tid >> 5;
    const int warpM = warp & 1;
    const int warpN = warp >> 1;
    const int kA    = lane & 3;
    const int grp   = lane >> 2;
    const int mBase = warpM * 64;
    const int nBase = warpN * 32;

    if (EPI == 0 || EPI == 3 || EPI == 4) outF += (long)bz * sC;

    Ah += (long)bz * sA;  Al += (long)bz * sA;
    Bh += (long)bz * sB;  Bl += (long)bz * sB;

    int Keff = K;
    if (MASKK) Keff = (brow < 8) ? 1024 : (brow + 1) * 128;

    // ---- gmem loader coords ----
    const int row = tid >> 1;
    const int hf  = tid & 1;
    const __nv_bfloat16* agH = Ah + (long)(brow * 128 + row) * lda + hf * 16;
    const __nv_bfloat16* agL = Al + (long)(brow * 128 + row) * lda + hf * 16;
    const __nv_bfloat16* bgH = Bh + (long)(bcol * 128 + row) * ldb + hf * 16;
    const __nv_bfloat16* bgL = Bl + (long)(bcol * 128 + row) * ldb + hf * 16;
    const int dstw = row * PW + hf * 8;

    // ---- ldmatrix per-lane address pieces ----
    const int t4 = lane >> 3;
    const int r8 = lane & 7;
    const int aHalfBase = (mBase + (t4 & 1) * 8 + r8) * 40 + (t4 >> 1) * 8;
    const int bHalfBase = (nBase + (t4 >> 1) * 8 + r8) * 40 + (t4 & 1) * 8;

    const unsigned smBase = (unsigned)__cvta_generic_to_shared(sm);

    float c[4][4][4];
#pragma unroll
    for (int mt = 0; mt < 4; mt++)
#pragma unroll
        for (int nt = 0; nt < 4; nt++)
#pragma unroll
            for (int i = 0; i < 4; i++) c[mt][nt][i] = 0.f;

    // ---- preload stage 0 ----
    {
        cp16(sm + 0 * TILEW + dstw, agH);      cp16(sm + 0 * TILEW + dstw + 4, agH + 8);
        cp16(sm + 2 * TILEW + dstw, agL);      cp16(sm + 2 * TILEW + dstw + 4, agL + 8);
        cp16(sm + 4 * TILEW + dstw, bgH);      cp16(sm + 4 * TILEW + dstw + 4, bgH + 8);
        cp16(sm + 6 * TILEW + dstw, bgL);      cp16(sm + 6 * TILEW + dstw + 4, bgL + 8);
        cp_commit();
        cp_wait0();
    }
    __syncthreads();

    const int nstages = Keff >> 5;      // BK = 32
    int buf = 0;
    for (int t = 0; t < nstages; ++t) {
        const bool more = (t + 1) < nstages;
        if (more) {
            const int k0 = (t + 1) * 32;
            const int nb = buf ^ 1;
            cp16(sm + nb * TILEW + dstw, agH + k0);
            cp16(sm + nb * TILEW + dstw + 4, agH + k0 + 8);
            cp16(sm + (2 + nb) * TILEW + dstw, agL + k0);
            cp16(sm + (2 + nb) * TILEW + dstw + 4, agL + k0 + 8);
            cp16(sm + (4 + nb) * TILEW + dstw, bgH + k0);
            cp16(sm + (4 + nb) * TILEW + dstw + 4, bgH + k0 + 8);
            cp16(sm + (6 + nb) * TILEW + dstw, bgL + k0);
            cp16(sm + (6 + nb) * TILEW + dstw + 4, bgL + k0 + 8);
            cp_commit();
        }

        const unsigned aH0 = smBase + (buf * TILEW) * 4       + aHalfBase * 2;
        const unsigned aL0 = smBase + ((2 + buf) * TILEW) * 4 + aHalfBase * 2;
        const unsigned bH0 = smBase + ((4 + buf) * TILEW) * 4 + bHalfBase * 2;
        const unsigned bL0 = smBase + ((6 + buf) * TILEW) * 4 + bHalfBase * 2;

#pragma unroll
        for (int ks = 0; ks < 2; ks++) {
            const int ko = ks * 32;

            unsigned ah[4][4];
#pragma unroll
            for (int mt = 0; mt < 4; mt++)
                ldsm4(ah[mt][0], ah[mt][1], ah[mt][2], ah[mt][3],
                      aH0 + mt * (16 * 40 * 2) + ko);

            unsigned bh[4][2];
#pragma unroll
            for (int np = 0; np < 2; np++)
                ldsm4(bh[2 * np][0], bh[2 * np][1], bh[2 * np + 1][0], bh[2 * np + 1][1],
                      bH0 + np * (16 * 40 * 2) + ko);

            // issue bl loads early so the hl MMA group never stalls mid-slab
            unsigned bl[4][2];
#pragma unroll
            for (int np = 0; np < 2; np++)
                ldsm4(bl[2 * np][0], bl[2 * np][1], bl[2 * np + 1][0], bl[2 * np + 1][1],
                      bL0 + np * (16 * 40 * 2) + ko);

#pragma unroll
            for (int mt = 0; mt < 4; mt++)
#pragma unroll
                for (int nt = 0; nt < 4; nt++)
                    mma_bf16(c[mt][nt][0], c[mt][nt][1], c[mt][nt][2], c[mt][nt][3],
                             ah[mt][0], ah[mt][1], ah[mt][2], ah[mt][3],
                             bh[nt][0], bh[nt][1]);

#pragma unroll
            for (int mt = 0; mt < 4; mt++)
#pragma unroll
                for (int nt = 0; nt < 4; nt++)
                    mma_bf16(c[mt][nt][0], c[mt][nt][1], c[mt][nt][2], c[mt][nt][3],
                             ah[mt][0], ah[mt][1], ah[mt][2], ah[mt][3],
                             bl[nt][0], bl[nt][1]);

            unsigned al[4][4];
#pragma unroll
            for (int mt = 0; mt < 4; mt++)
                ldsm4(al[mt][0], al[mt][1], al[mt][2], al[mt][3],
                      aL0 + mt * (16 * 40 * 2) + ko);

#pragma unroll
            for (int mt = 0; mt < 4; mt++)
#pragma unroll
                for (int nt = 0; nt < 4; nt++)
                    mma_bf16(c[mt][nt][0], c[mt][nt][1], c[mt][nt][2], c[mt][nt][3],
                             al[mt][0], al[mt][1], al[mt][2], al[mt][3],
                             bh[nt][0], bh[nt][1]);
        }

        if (more) {
            cp_wait0();
            __syncthreads();
            buf ^= 1;
        }
    }

    // ---- epilogue ----
#pragma unroll
    for (int mt = 0; mt < 4; mt++) {
        const int gr0 = brow * 128 + mBase + mt * 16 + grp;
#pragma unroll
        for (int nt = 0; nt < 4; nt++) {
            const int gc = bcol * 128 + nBase + nt * 8 + kA * 2;
#pragma unroll
            for (int h = 0; h < 2; h++) {
                const int gr = gr0 + h * 8;
                float v0 = c[mt][nt][h * 2 + 0];
                float v1 = c[mt][nt][h * 2 + 1];

                if (EPI == 0) {
                    *reinterpret_cast<float2*>(&outF[(long)gr * ldc + gc]) = make_float2(v0, v1);
                } else if (EPI == 4) {
                    const int half = N >> 1;
                    const bool ok0 = (gr < half) ? (gc < half) : (gc <= gr);
                    const bool ok1 = (gr < half) ? (gc + 1 < half) : (gc + 1 <= gr);
                    v0 = alpha * v0 + (ok0 ? 0.f : -1000.f);
                    v1 = alpha * v1 + (ok1 ? 0.f : -1000.f);
                    *reinterpret_cast<float2*>(&outF[(long)gr * ldc + gc]) = make_float2(v0, v1);
                } else if (EPI == 1) {
                    v0 += bias[gc];
                    v1 += bias[gc + 1];
                    __nv_bfloat16 h0, l0, h1, l1;
                    split_bf(v0, h0, l0);
                    split_bf(v1, h1, l1);
                    const int seg = gc >> 9;
                    const int col = gc & 511;
                    if (seg == 0) {
                        const long idx = ((long)bz * NN_ + gr) * CC + col;
                        *reinterpret_cast<unsigned*>(&g_qh[idx]) = pack2(h0, h1);
                        *reinterpret_cast<unsigned*>(&g_ql[idx]) = pack2(l0, l1);
                    } else if (seg == 1) {
                        const long idx = ((long)bz * NN_ + gr) * CC + col;
                        *reinterpret_cast<unsigned*>(&g_kh[idx]) = pack2(h0, h1);
                        *reinterpret_cast<unsigned*>(&g_kl[idx]) = pack2(l0, l1);
                    } else {
                        const long i0 = ((long)bz * CC + col) * NN_ + gr;
                        const long i1 = ((long)bz * CC + col + 1) * NN_ + gr;
                        g_vth[i0] = h0; g_vtl[i0] = l0;
                        g_vth[i1] = h1; g_vtl[i1] = l1;
                    }
                } else if (EPI == 2) {
                    v0 += bias[gc];
                    v1 += bias[gc + 1];
                    v0 = 0.5f * v0 * (1.f + erff(v0 * 0.70710678118654752f));
                    v1 = 0.5f * v1 * (1.f + erff(v1 * 0.70710678118654752f));
                    __nv_bfloat16 h0, l0, h1, l1;
                    split_bf(v0, h0, l0);
                    split_bf(v1, h1, l1);
                    const long idx = (long)bz * sC + (long)gr * ldc + gc;
                    *reinterpret_cast<unsigned*>(&g_hh[idx]) = pack2(h0, h1);
                    *reinterpret_cast<unsigned*>(&g_hl[idx]) = pack2(l0, l1);
                } else {  // EPI == 3
                    const float* rr = resid + (long)bz * sC + (long)gr * ldc + gc;
                    v0 += bias[gc] + rr[0];
                    v1 += bias[gc + 1] + rr[1];
                    *reinterpret_cast<float2*>(&outF[(long)gr * ldc + gc]) = make_float2(v0, v1);
                    __nv_bfloat16 h0, l0, h1, l1;
                    split_bf(v0, h0, l0);
                    split_bf(v1, h1, l1);
                    const long idx = (long)bz * sC + (long)gr * ldc + gc;
                    *reinterpret_cast<unsigned*>(&g_xh[idx]) = pack2(h0, h1);
                    *reinterpret_cast<unsigned*>(&g_xl[idx]) = pack2(l0, l1);
                }
            }
        }
    }
}

// Weight transpose + bf16 hi/lo split: W [L][K][N] fp32 -> T [L][N][K] bf16 x2
__global__ void wtrans_k(const float* __restrict__ W,
                         __nv_bfloat16* __restrict__ Th, __nv_bfloat16* __restrict__ Tl,
                         int K, int N)
{
    __shared__ float t[32][33];
    const int n0 = blockIdx.x * 32, k0 = blockIdx.y * 32, l = blockIdx.z;
    const int tx = threadIdx.x, ty = threadIdx.y;
    const float* Wl = W + (long)l * K * N;
#pragma unroll
    for (int i = 0; i < 4; i++)
        t[ty + 8 * i][tx] = Wl[(long)(k0 + ty + 8 * i) * N + n0 + tx];
    __syncthreads();
    const long ob = (long)l * N * K;
#pragma unroll
    for (int i = 0; i < 4; i++) {
        const int n = n0 + ty + 8 * i;
        float v = t[tx][ty + 8 * i];
        __nv_bfloat16 h, lo;
        split_bf(v, h, lo);
        Th[ob + (long)n * K + k0 + tx] = h;
        Tl[ob + (long)n * K + k0 + tx] = lo;
    }
}

// Initial x -> bf16 hi/lo planes
__global__ void xcvt_k(const float* __restrict__ x,
                       __nv_bfloat16* __restrict__ Xh, __nv_bfloat16* __restrict__ Xl)
{
    const long i = (long)blockIdx.x * 256 + threadIdx.x;
    float4 v = reinterpret_cast<const float4*>(x)[i];
    __nv_bfloat16 h0, l0, h1, l1, h2, l2, h3, l3;
    split_bf(v.x, h0, l0); split_bf(v.y, h1, l1);
    split_bf(v.z, h2, l2); split_bf(v.w, h3, l3);
    unsigned* ph = reinterpret_cast<unsigned*>(Xh) + i * 2;
    unsigned* pl = reinterpret_cast<unsigned*>(Xl) + i * 2;
    ph[0] = pack2(h0, h1); ph[1] = pack2(h2, h3);
    pl[0] = pack2(l0, l1); pl[1] = pack2(l2, l3);
}

// Mask-aware vectorized row softmax: row i has Klim valid cols; thread t owns
// the contiguous 8-col chunk at t*8 (Klim is a multiple of 128 -> chunks are
// entirely in or out). Masked S tiles are never read.
__global__ __launch_bounds__(256)
void softmax_k(const float* __restrict__ S,
               __nv_bfloat16* __restrict__ Ph, __nv_bfloat16* __restrict__ Pl)
{
    const int rowg = blockIdx.x;
    const int i = rowg & (NN_ - 1);
    const int Klim = (i < 1024) ? 1024 : (((i >> 7) + 1) << 7);
    const float* p = S + (size_t)rowg * NN_;
    const int t = threadIdx.x;
    const int base = t * 8;
    const bool act = base < Klim;

    float v[8];
    float mx = -1e30f;
    if (act) {
        float4 a = *reinterpret_cast<const float4*>(p + base);
        float4 b = *reinterpret_cast<const float4*>(p + base + 4);
        v[0] = a.x; v[1] = a.y; v[2] = a.z; v[3] = a.w;
        v[4] = b.x; v[5] = b.y; v[6] = b.z; v[7] = b.w;
#pragma unroll
        for (int u = 0; u < 8; u++) mx = fmaxf(mx, v[u]);
    }

    __shared__ float red[8];
#pragma unroll
    for (int o = 16; o > 0; o >>= 1) mx = fmaxf(mx, __shfl_xor_sync(0xffffffffu, mx, o));
    if ((t & 31) == 0) red[t >> 5] = mx;
    __syncthreads();
    mx = red[0];
#pragma unroll
    for (int i2 = 1; i2 < 8; i2++) mx = fmaxf(mx, red[i2]);

    float s = 0.f;
    if (act) {
#pragma unroll
        for (int u = 0; u < 8; u++) {
            v[u] = __expf(v[u] - mx);
            s += v[u];
        }
    }
#pragma unroll
    for (int o = 16; o > 0; o >>= 1) s += __shfl_xor_sync(0xffffffffu, s, o);
    __syncthreads();
    if ((t & 31) == 0) red[t >> 5] = s;
    __syncthreads();
    s = red[0];
#pragma unroll
    for (int i2 = 1; i2 < 8; i2++) s += red[i2];

    if (act) {
        const float inv = 1.f / s;
        unsigned ph[4], pl[4];
#pragma unroll
        for (int jp = 0; jp < 4; jp++) {
            __nv_bfloat16 h0, l0, h1, l1;
            split_bf(v[2 * jp] * inv, h0, l0);
            split_bf(v[2 * jp + 1] * inv, h1, l1);
            ph[jp] = pack2(h0, h1);
            pl[jp] = pack2(l0, l1);
        }
        const size_t ob = (size_t)rowg * NN_ + base;
        *reinterpret_cast<uint4*>(Ph + ob) = *reinterpret_cast<uint4*>(ph);
        *reinterpret_cast<uint4*>(Pl + ob) = *reinterpret_cast<uint4*>(pl);
    }
}

// LayerNorm over C=512 -> y bf16 hi/lo
__global__ __launch_bounds__(128)
void ln_k(const float* __restrict__ X, const float* __restrict__ g,
          const float* __restrict__ b,
          __nv_bfloat16* __restrict__ Yh, __nv_bfloat16* __restrict__ Yl)
{
    const int C = 512;
    const float* x = X + (size_t)blockIdx.x * C;
    const int t = threadIdx.x;

    float4 v = *reinterpret_cast<const float4*>(x + t * 4);
    float s = v.x + v.y + v.z + v.w;

    __shared__ float red[4];
#pragma unroll
    for (int o = 16; o > 0; o >>= 1) s += __shfl_xor_sync(0xffffffffu, s, o);
    if ((t & 31) == 0) red[t >> 5] = s;
    __syncthreads();
    const float mean = (red[0] + red[1] + red[2] + red[3]) * (1.f / 512.f);

    const float dx = v.x - mean, dy = v.y - mean, dz = v.z - mean, dw = v.w - mean;
    float q = dx * dx + dy * dy + dz * dz + dw * dw;
#pragma unroll
    for (int o = 16; o > 0; o >>= 1) q += __shfl_xor_sync(0xffffffffu, q, o);
    __syncthreads();
    if ((t & 31) == 0) red[t >> 5] = q;
    __syncthreads();
    const float var = (red[0] + red[1] + red[2] + red[3]) * (1.f / 512.f);
    const float rstd = rsqrtf(var + 1e-5f);

    float4 gg = *reinterpret_cast<const float4*>(g + t * 4);
    float4 bb = *reinterpret_cast<const float4*>(b + t * 4);
    float o0 = dx * rstd * gg.x + bb.x;
    float o1 = dy * rstd * gg.y + bb.y;
    float o2 = dz * rstd * gg.z + bb.z;
    float o3 = dw * rstd * gg.w + bb.w;

    __nv_bfloat16 h0, l0, h1, l1, h2, l2, h3, l3;
    split_bf(o0, h0, l0); split_bf(o1, h1, l1);
    split_bf(o2, h2, l2); split_bf(o3, h3, l3);
    const long base = (long)blockIdx.x * C + t * 4;
    unsigned* ph = reinterpret_cast<unsigned*>(Yh + base);
    unsigned* pl = reinterpret_cast<unsigned*>(Yl + base);
    ph[0] = pack2(h0, h1); ph[1] = pack2(h2, h3);
    pl[0] = pack2(l0, l1); pl[1] = pack2(l2, l3);
}

extern "C" void kernel_launch(void* const* d_in, const int* in_sizes, int n_in,
                              void* d_out, int out_size)
{
    const float* x_in  = (const float*)d_in[0];
    const float* qkv_w = (const float*)d_in[1];
    const float* qkv_b = (const float*)d_in[2];
    const float* ln_g  = (const float*)d_in[3];
    const float* ln_b  = (const float*)d_in[4];
    const float* fc1_w = (const float*)d_in[5];
    const float* fc1_b = (const float*)d_in[6];
    const float* fc2_w = (const float*)d_in[7];
    const float* fc2_b = (const float*)d_in[8];
    float* x = (float*)d_out;

    float* S;
    __nv_bfloat16 *xh, *xl, *qh, *ql, *kh, *kl, *vth, *vtl, *Ph, *Pl, *yh, *yl, *hh, *hl;
    __nv_bfloat16 *wqh, *wql, *w1h, *w1l, *w2h, *w2l;
    cudaGetSymbolAddress((void**)&S,   g_S);
    cudaGetSymbolAddress((void**)&xh,  g_xh);  cudaGetSymbolAddress((void**)&xl,  g_xl);
    cudaGetSymbolAddress((void**)&qh,  g_qh);  cudaGetSymbolAddress((void**)&ql,  g_ql);
    cudaGetSymbolAddress((void**)&kh,  g_kh);  cudaGetSymbolAddress((void**)&kl,  g_kl);
    cudaGetSymbolAddress((void**)&vth, g_vth); cudaGetSymbolAddress((void**)&vtl, g_vtl);
    cudaGetSymbolAddress((void**)&Ph,  g_Ph);  cudaGetSymbolAddress((void**)&Pl,  g_Pl);
    cudaGetSymbolAddress((void**)&yh,  g_yh);  cudaGetSymbolAddress((void**)&yl,  g_yl);
    cudaGetSymbolAddress((void**)&hh,  g_hh);  cudaGetSymbolAddress((void**)&hl,  g_hl);
    cudaGetSymbolAddress((void**)&wqh, g_wqh); cudaGetSymbolAddress((void**)&wql, g_wql);
    cudaGetSymbolAddress((void**)&w1h, g_w1h); cudaGetSymbolAddress((void**)&w1l, g_w1l);
    cudaGetSymbolAddress((void**)&w2h, g_w2h); cudaGetSymbolAddress((void**)&w2l, g_w2l);

    cudaFuncSetAttribute(gemm_bf16<0, true>,  cudaFuncAttributeMaxDynamicSharedMemorySize, GEMM_SMEM);
    cudaFuncSetAttribute(gemm_bf16<1, false>, cudaFuncAttributeMaxDynamicSharedMemorySize, GEMM_SMEM);
    cudaFuncSetAttribute(gemm_bf16<2, false>, cudaFuncAttributeMaxDynamicSharedMemorySize, GEMM_SMEM);
    cudaFuncSetAttribute(gemm_bf16<3, false>, cudaFuncAttributeMaxDynamicSharedMemorySize, GEMM_SMEM);
    cudaFuncSetAttribute(gemm_bf16<4, false>, cudaFuncAttributeMaxDynamicSharedMemorySize, GEMM_SMEM);

    const int Bn = 8, Nn = 2048, Cn = 512;
    const long xs = (long)Nn * Cn;
    const float scale = 0.044194173824159216f;  // 512^-0.5

    cudaMemcpyAsync(x, x_in, sizeof(float) * Bn * Nn * Cn, cudaMemcpyDeviceToDevice);

    // one-time pre-split of weights (transposed to [N][K]) and initial x
    wtrans_k<<<dim3(48, 16, 5), dim3(32, 8)>>>(qkv_w, wqh, wql, 512, 1536);
    wtrans_k<<<dim3(32, 16, 5), dim3(32, 8)>>>(fc1_w, w1h, w1l, 512, 1024);
    wtrans_k<<<dim3(16, 32, 5), dim3(32, 8)>>>(fc2_w, w2h, w2l, 1024, 512);
    xcvt_k<<<(int)((long)Bn * Nn * Cn / 4 / 256), 256>>>(x_in, xh, xl);

    for (int l = 0; l < 5; l++) {
        // qkv (EPI=1)
        gemm_bf16<1, false><<<dim3(12, 16, 8), 256, GEMM_SMEM>>>(
            xh, xl, wqh + (long)l * 1536 * 512, wql + (long)l * 1536 * 512,
            qkv_b + l * 3 * Cn, nullptr, nullptr,
            Nn, 1536, 512, 512, 512, 0, xs, 0, 0, 1.f);

        // S = scale*q@k^T + mask (EPI=4); fully masked tiles skipped entirely
        gemm_bf16<4, false><<<dim3(16, 16, 8), 256, GEMM_SMEM>>>(
            qh, ql, kh, kl, nullptr, nullptr, S,
            Nn, Nn, 512, 512, 512, Nn, xs, xs, (long)Nn * Nn, scale);

        // P = softmax(S) (mask-aware prefix)
        softmax_k<<<Bn * Nn, 256>>>(S, Ph, Pl);

        // x = P @ v (EPI=0, K-trunc)
        gemm_bf16<0, true><<<dim3(4, 16, 8), 256, GEMM_SMEM>>>(
            Ph, Pl, vth, vtl, nullptr, nullptr, x,
            Nn, Cn, Nn, Nn, Nn, Cn, (long)Nn * Nn, (long)Cn * Nn, xs, 1.f);

        // y = layernorm(x)
        ln_k<<<Bn * Nn, 128>>>(x, ln_g + l * Cn, ln_b + l * Cn, yh, yl);

        // h = gelu(y @ fc1 + b) (EPI=2)
        gemm_bf16<2, false><<<dim3(8, 16, 8), 256, GEMM_SMEM>>>(
            yh, yl, w1h + (long)l * 1024 * 512, w1l + (long)l * 1024 * 512,
            fc1_b + l * 2 * Cn, nullptr, nullptr,
            Nn, 1024, 512, 512, 512, 1024, xs, 0, (long)Nn * 1024, 1.f);

        // x = x + h @ fc2 + b (EPI=3)
        gemm_bf16<3, false><<<dim3(4, 16, 8), 256, GEMM_SMEM>>>(
            hh, hl, w2h + (long)l * 512 * 1024, w2l + (long)l * 512 * 1024,
            fc2_b + l * Cn, x, x,
            Nn, Cn, 1024, 1024, 1024, Cn, (long)Nn * 1024, 0, xs, 1.f);
    }
}